// round 14
// baseline (speedup 1.0000x reference)
#include <cuda_runtime.h>
#include <cuda_bf16.h>
#include <cstdint>

#define TLEN 4096
#define DIM 1024
#define NH 16
#define HD 64
#define QKV_N 3072
#define PAD 72      // bf16 elems per smem row (144 B)
#define PADV 136    // bf16 elems per smem row for V^T tiles (272 B)
#define QSCALE 0.18033688011112042f   // 0.125 * log2(e)

// ---------------- scratch (allocation-free) ----------------
__device__ __nv_bfloat16 g_xs_hi[(size_t)TLEN * DIM],  g_xs_lo[(size_t)TLEN * DIM];
__device__ __nv_bfloat16 g_wi_hi[(size_t)QKV_N * DIM], g_wi_lo[(size_t)QKV_N * DIM];
__device__ __nv_bfloat16 g_wo_hi[(size_t)DIM * DIM],   g_wo_lo[(size_t)DIM * DIM];
__device__ __nv_bfloat16 g_qkv_hi[(size_t)TLEN * QKV_N], g_qkv_lo[(size_t)TLEN * QKV_N];
__device__ __nv_bfloat16 g_vt_hi[(size_t)NH * HD * TLEN], g_vt_lo[(size_t)NH * HD * TLEN];
__device__ __nv_bfloat16 g_at_hi[(size_t)TLEN * DIM],  g_at_lo[(size_t)TLEN * DIM];
__device__ float g_attn[(size_t)TLEN * DIM];
__device__ float g_attn2[(size_t)TLEN * DIM];
__device__ float g_sum[NH];

// ---------------- helpers ----------------
__device__ __forceinline__ uint32_t smem_u32(const void* p) {
    uint32_t a;
    asm("{ .reg .u64 t; cvta.to.shared.u64 t, %1; cvt.u32.u64 %0, t; }" : "=r"(a) : "l"(p));
    return a;
}
__device__ __forceinline__ uint32_t pkf(float a, float b) {
    uint32_t r;
    asm("cvt.rn.bf16x2.f32 %0, %1, %2;" : "=r"(r) : "f"(b), "f"(a));
    return r;
}
__device__ __forceinline__ float bf_lo_as_f(uint32_t u) { return __uint_as_float(u << 16); }
__device__ __forceinline__ float bf_hi_as_f(uint32_t u) { return __uint_as_float(u & 0xffff0000u); }
__device__ __forceinline__ float ex2f(float x) {
    float y;
    asm("ex2.approx.f32 %0, %1;" : "=f"(y) : "f"(x));
    return y;
}

__device__ __forceinline__ void ldsm_x4(uint32_t* r, uint32_t addr) {
    asm volatile("ldmatrix.sync.aligned.m8n8.x4.shared.b16 {%0,%1,%2,%3}, [%4];"
                 : "=r"(r[0]), "=r"(r[1]), "=r"(r[2]), "=r"(r[3]) : "r"(addr));
}
__device__ __forceinline__ void mma16816(float* c, const uint32_t* a, uint32_t b0, uint32_t b1) {
    asm volatile(
        "mma.sync.aligned.m16n8k16.row.col.f32.bf16.bf16.f32 "
        "{%0,%1,%2,%3}, {%4,%5,%6,%7}, {%8,%9}, {%0,%1,%2,%3};"
        : "+f"(c[0]), "+f"(c[1]), "+f"(c[2]), "+f"(c[3])
        : "r"(a[0]), "r"(a[1]), "r"(a[2]), "r"(a[3]), "r"(b0), "r"(b1));
}
__device__ __forceinline__ void cp16(uint32_t dst, const void* src) {
    asm volatile("cp.async.cg.shared.global [%0], [%1], 16;" :: "r"(dst), "l"(src));
}
#define CP_COMMIT() asm volatile("cp.async.commit_group;" ::: "memory")
#define CP_WAIT(N)  asm volatile("cp.async.wait_group %0;" :: "n"(N) : "memory")

__global__ void init_kernel() {
    if (threadIdx.x < NH) g_sum[threadIdx.x] = 0.0f;
}

// fp32 -> split bf16 hi/lo planes
__global__ void __launch_bounds__(256) split_f32(const float* __restrict__ src,
                                                 __nv_bfloat16* __restrict__ hi,
                                                 __nv_bfloat16* __restrict__ lo, int n4) {
    int i = blockIdx.x * 256 + threadIdx.x;
    if (i >= n4) return;
    float4 v = ((const float4*)src)[i];
    uint32_t h0 = pkf(v.x, v.y), h1 = pkf(v.z, v.w);
    uint32_t l0 = pkf(v.x - bf_lo_as_f(h0), v.y - bf_hi_as_f(h0));
    uint32_t l1 = pkf(v.z - bf_lo_as_f(h1), v.w - bf_hi_as_f(h1));
    ((uint2*)hi)[i] = make_uint2(h0, h1);
    ((uint2*)lo)[i] = make_uint2(l0, l1);
}

// V^T per head: vt[h][d][s] = V[s][d], both planes
__global__ void __launch_bounds__(256) transpose_v() {
    __shared__ ushort th[64][65], tl[64][65];
    int h = blockIdx.y, s0 = blockIdx.x * 64;
    int tid = threadIdx.x;
#pragma unroll
    for (int i = 0; i < 16; i++) {
        int slot = tid + i * 256;
        int s = slot >> 6, d = slot & 63;
        size_t src = (size_t)(s0 + s) * QKV_N + 2 * DIM + h * HD + d;
        th[s][d] = ((const ushort*)g_qkv_hi)[src];
        tl[s][d] = ((const ushort*)g_qkv_lo)[src];
    }
    __syncthreads();
#pragma unroll
    for (int i = 0; i < 16; i++) {
        int slot = tid + i * 256;
        int d = slot >> 6, s = slot & 63;
        size_t dst = ((size_t)h * HD + d) * TLEN + s0 + s;
        ((ushort*)g_vt_hi)[dst] = th[s][d];
        ((ushort*)g_vt_lo)[dst] = tl[s][d];
    }
}

// ---------------- split-bf16 3-pass GEMM: 64x128 tile, 2 CTAs/SM (R12, untouched) ----------------
template <bool SPLIT_OUT>
__global__ void __launch_bounds__(256, 2) gemm_bf16(
    const __nv_bfloat16* __restrict__ Ahi, const __nv_bfloat16* __restrict__ Alo, int lda,
    const __nv_bfloat16* __restrict__ Bhi, const __nv_bfloat16* __restrict__ Blo, int ldb,
    float* __restrict__ Cf, __nv_bfloat16* __restrict__ Chi, __nv_bfloat16* __restrict__ Clo,
    int ldc, int K, int qcols)
{
    extern __shared__ char smem[];
    uint32_t su = smem_u32(smem);
    constexpr uint32_t PLA = 64 * PAD * 2;
    constexpr uint32_t PLB = 128 * PAD * 2;
    constexpr uint32_t STG = 2 * PLA + 2 * PLB;

    int m0 = blockIdx.y * 64, n0 = blockIdx.x * 128;
    int tid = threadIdx.x, wid = tid >> 5, lid = tid & 31;
    int wm = (wid & 1) * 32, wn = (wid >> 1) * 32;
    int g = lid >> 2, t2 = (lid & 3) * 2, rsel = lid & 7, mat = lid >> 3;

    uint32_t a_off[2], b2_off[2];
#pragma unroll
    for (int mf = 0; mf < 2; mf++)
        a_off[mf] = (uint32_t)(((wm + mf * 16 + (mat & 1) * 8 + rsel) * PAD + (mat >> 1) * 8) * 2);
#pragma unroll
    for (int p = 0; p < 2; p++)
        b2_off[p] = (uint32_t)(((wn + p * 16 + (mat >> 1) * 8 + rsel) * PAD + (mat & 1) * 8) * 2);

    auto issue = [&](int kc, int st) {
        uint32_t base = su + st * STG;
        int k0 = kc * 64;
#pragma unroll
        for (int i = 0; i < 2; i++) {
            int idx = tid + i * 256;
            int row = idx >> 3, ch = idx & 7;
            uint32_t d = base + (uint32_t)((row * PAD + ch * 8) * 2);
            cp16(d,       Ahi + (size_t)(m0 + row) * lda + k0 + ch * 8);
            cp16(d + PLA, Alo + (size_t)(m0 + row) * lda + k0 + ch * 8);
        }
#pragma unroll
        for (int i = 0; i < 4; i++) {
            int idx = tid + i * 256;
            int row = idx >> 3, ch = idx & 7;
            uint32_t d = base + 2 * PLA + (uint32_t)((row * PAD + ch * 8) * 2);
            cp16(d,       Bhi + (size_t)(n0 + row) * ldb + k0 + ch * 8);
            cp16(d + PLB, Blo + (size_t)(n0 + row) * ldb + k0 + ch * 8);
        }
        CP_COMMIT();
    };

    float acc[2][4][4];
#pragma unroll
    for (int mf = 0; mf < 2; mf++)
#pragma unroll
        for (int nf = 0; nf < 4; nf++)
#pragma unroll
            for (int j = 0; j < 4; j++) acc[mf][nf][j] = 0.0f;

    int NKC = K / 64;
    issue(0, 0);
    for (int kc = 0; kc < NKC; kc++) {
        int st = kc & 1;
        if (kc + 1 < NKC) { issue(kc + 1, st ^ 1); CP_WAIT(1); }
        else              { CP_WAIT(0); }
        __syncthreads();
        uint32_t ah = su + st * STG, al = ah + PLA;
        uint32_t bh = su + st * STG + 2 * PLA, bl = bh + PLB;
#pragma unroll
        for (int ks = 0; ks < 4; ks++) {
            uint32_t kb = (uint32_t)(ks * 32);
            uint32_t fh[2][4], fl[2][4];
            ldsm_x4(fh[0], ah + a_off[0] + kb);
            ldsm_x4(fh[1], ah + a_off[1] + kb);
            ldsm_x4(fl[0], al + a_off[0] + kb);
            ldsm_x4(fl[1], al + a_off[1] + kb);
#pragma unroll
            for (int p = 0; p < 2; p++) {
                uint32_t bb[4], cc[4];
                ldsm_x4(bb, bh + b2_off[p] + kb);
                mma16816(acc[0][2 * p],     fh[0], bb[0], bb[1]);
                mma16816(acc[1][2 * p],     fh[1], bb[0], bb[1]);
                mma16816(acc[0][2 * p + 1], fh[0], bb[2], bb[3]);
                mma16816(acc[1][2 * p + 1], fh[1], bb[2], bb[3]);
                mma16816(acc[0][2 * p],     fl[0], bb[0], bb[1]);
                mma16816(acc[1][2 * p],     fl[1], bb[0], bb[1]);
                mma16816(acc[0][2 * p + 1], fl[0], bb[2], bb[3]);
                mma16816(acc[1][2 * p + 1], fl[1], bb[2], bb[3]);
                ldsm_x4(cc, bl + b2_off[p] + kb);
                mma16816(acc[0][2 * p],     fh[0], cc[0], cc[1]);
                mma16816(acc[1][2 * p],     fh[1], cc[0], cc[1]);
                mma16816(acc[0][2 * p + 1], fh[0], cc[2], cc[3]);
                mma16816(acc[1][2 * p + 1], fh[1], cc[2], cc[3]);
            }
        }
        __syncthreads();
    }

    // epilogue
#pragma unroll
    for (int mf = 0; mf < 2; mf++) {
        int r0 = m0 + wm + mf * 16 + g;
#pragma unroll
        for (int nf = 0; nf < 4; nf++) {
            int col = n0 + wn + nf * 8 + t2;
            float sc = 1.0f;
            if (SPLIT_OUT && col < qcols) sc = QSCALE;
            float v0 = acc[mf][nf][0] * sc, v1 = acc[mf][nf][1] * sc;
            float v2 = acc[mf][nf][2] * sc, v3 = acc[mf][nf][3] * sc;
            if (SPLIT_OUT) {
                uint32_t h0 = pkf(v0, v1);
                uint32_t l0 = pkf(v0 - bf_lo_as_f(h0), v1 - bf_hi_as_f(h0));
                *(uint32_t*)(Chi + (size_t)r0 * ldc + col) = h0;
                *(uint32_t*)(Clo + (size_t)r0 * ldc + col) = l0;
                uint32_t h1 = pkf(v2, v3);
                uint32_t l1 = pkf(v2 - bf_lo_as_f(h1), v3 - bf_hi_as_f(h1));
                *(uint32_t*)(Chi + (size_t)(r0 + 8) * ldc + col) = h1;
                *(uint32_t*)(Clo + (size_t)(r0 + 8) * ldc + col) = l1;
            } else {
                *(float2*)(Cf + (size_t)r0 * ldc + col) = make_float2(v0, v1);
                *(float2*)(Cf + (size_t)(r0 + 8) * ldc + col) = make_float2(v2, v3);
            }
        }
    }
}

// ---------------- fused attention (Q-hi AND Q-lo hoisted to registers) ----------------
__global__ void __launch_bounds__(256) flash_attn()
{
    extern __shared__ char smem[];
    __shared__ float ssum;
    uint32_t su = smem_u32(smem);
    constexpr uint32_t QLO   = 128 * PAD * 2;
    constexpr uint32_t KBASE = 2 * 128 * PAD * 2;
    constexpr uint32_t KSTG  = 2 * 128 * PAD * 2;
    constexpr uint32_t VBASE = KBASE + 2 * KSTG;
    constexpr uint32_t VPL   = 64 * PADV * 2;
    constexpr uint32_t VSTG  = 2 * VPL;
    constexpr int NSPLIT_T = (TLEN / 128) / 2;   // 16 key tiles per split

    int h = blockIdx.y;
    int m0 = blockIdx.x * 128;
    int z = blockIdx.z;
    int tbase = z * NSPLIT_T;
    float* Oglob = z ? g_attn2 : g_attn;
    int tid = threadIdx.x, wid = tid >> 5, lid = tid & 31;
    int wm = (wid & 3) * 32, wn = (wid >> 2) * 64;
    int g = lid >> 2, t2 = (lid & 3) * 2, rsel = lid & 7, mat = lid >> 3;

    // load Q tile planes (pre-scaled by 0.125*log2e)
#pragma unroll
    for (int i = 0; i < 4; i++) {
        int idx = tid + i * 256;
        int row = idx >> 3, ch = idx & 7;
        size_t src = (size_t)(m0 + row) * QKV_N + h * HD + ch * 8;
        uint32_t d = (uint32_t)((row * PAD + ch * 8) * 2);
        *(uint4*)(smem + d)       = *(const uint4*)(g_qkv_hi + src);
        *(uint4*)(smem + QLO + d) = *(const uint4*)(g_qkv_lo + src);
    }
    if (tid == 0) ssum = 0.0f;

    uint32_t a_off[2], b2_off[4], v2_off[4];
#pragma unroll
    for (int mf = 0; mf < 2; mf++)
        a_off[mf] = (uint32_t)(((wm + mf * 16 + (mat & 1) * 8 + rsel) * PAD + (mat >> 1) * 8) * 2);
#pragma unroll
    for (int p = 0; p < 4; p++) {
        b2_off[p] = (uint32_t)(((wn + p * 16 + (mat >> 1) * 8 + rsel) * PAD + (mat & 1) * 8) * 2);
        v2_off[p] = (uint32_t)(((p * 16 + (mat >> 1) * 8 + rsel) * PADV + wn + (mat & 1) * 8) * 2);
    }

    auto issue = [&](int t, int st) {
        int s0 = t * 128;
        uint32_t kb = su + KBASE + st * KSTG;
#pragma unroll
        for (int i = 0; i < 4; i++) {
            int idx = tid + i * 256;
            int row = idx >> 3, ch = idx & 7;
            size_t src = (size_t)(s0 + row) * QKV_N + DIM + h * HD + ch * 8;
            uint32_t d = kb + (uint32_t)((row * PAD + ch * 8) * 2);
            cp16(d,                 g_qkv_hi + src);
            cp16(d + 128 * PAD * 2, g_qkv_lo + src);
        }
        uint32_t vb = su + VBASE + st * VSTG;
#pragma unroll
        for (int i = 0; i < 4; i++) {
            int idx = tid + i * 256;
            int dd = idx >> 4, ch = idx & 15;
            size_t src = ((size_t)h * HD + dd) * TLEN + s0 + ch * 8;
            uint32_t d = vb + (uint32_t)((dd * PADV + ch * 8) * 2);
            cp16(d,       g_vt_hi + src);
            cp16(d + VPL, g_vt_lo + src);
        }
        CP_COMMIT();
    };

    issue(tbase, 0);
    __syncthreads();

    // hoist BOTH Q planes' fragments (invariant over key tiles)
    uint32_t Qh[4][2][4], Ql[4][2][4];
#pragma unroll
    for (int ks = 0; ks < 4; ks++)
#pragma unroll
        for (int mf = 0; mf < 2; mf++) {
            ldsm_x4(Qh[ks][mf], su + a_off[mf] + ks * 32);
            ldsm_x4(Ql[ks][mf], su + QLO + a_off[mf] + ks * 32);
        }

    float O[2][8][4];
#pragma unroll
    for (int mf = 0; mf < 2; mf++)
#pragma unroll
        for (int nf = 0; nf < 8; nf++)
#pragma unroll
            for (int j = 0; j < 4; j++) O[mf][nf][j] = 0.0f;
    float sumE = 0.0f;

    for (int tt = 0; tt < NSPLIT_T; tt++) {
        int st = tt & 1;
        if (tt + 1 < NSPLIT_T) { issue(tbase + tt + 1, st ^ 1); CP_WAIT(1); }
        else                   { CP_WAIT(0); }
        __syncthreads();

        uint32_t kh = su + KBASE + st * KSTG, kl = kh + 128 * PAD * 2;
        uint32_t vh = su + VBASE + st * VSTG, vl = vh + VPL;

        // ---- S = Q @ K^T (3-pass, K frags loaded in pairs, Q all in regs) ----
        float E[2][8][4];
#pragma unroll
        for (int mf = 0; mf < 2; mf++)
#pragma unroll
            for (int nf = 0; nf < 8; nf++)
#pragma unroll
                for (int j = 0; j < 4; j++) E[mf][nf][j] = 0.0f;
#pragma unroll
        for (int ks = 0; ks < 4; ks++) {
            uint32_t kb = (uint32_t)(ks * 32);
#pragma unroll
            for (int p = 0; p < 4; p += 2) {
                uint32_t bb0[4], bb1[4], cc0[4], cc1[4];
                ldsm_x4(bb0, kh + b2_off[p] + kb);
                ldsm_x4(bb1, kh + b2_off[p + 1] + kb);
                ldsm_x4(cc0, kl + b2_off[p] + kb);
                ldsm_x4(cc1, kl + b2_off[p + 1] + kb);
                // pass 1: Qhi * Khi
                mma16816(E[0][2 * p],     Qh[ks][0], bb0[0], bb0[1]);
                mma16816(E[1][2 * p],     Qh[ks][1], bb0[0], bb0[1]);
                mma16816(E[0][2 * p + 1], Qh[ks][0], bb0[2], bb0[3]);
                mma16816(E[1][2 * p + 1], Qh[ks][1], bb0[2], bb0[3]);
                mma16816(E[0][2 * p + 2], Qh[ks][0], bb1[0], bb1[1]);
                mma16816(E[1][2 * p + 2], Qh[ks][1], bb1[0], bb1[1]);
                mma16816(E[0][2 * p + 3], Qh[ks][0], bb1[2], bb1[3]);
                mma16816(E[1][2 * p + 3], Qh[ks][1], bb1[2], bb1[3]);
                // pass 2: Qhi * Klo
                mma16816(E[0][2 * p],     Qh[ks][0], cc0[0], cc0[1]);
                mma16816(E[1][2 * p],     Qh[ks][1], cc0[0], cc0[1]);
                mma16816(E[0][2 * p + 1], Qh[ks][0], cc0[2], cc0[3]);
                mma16816(E[1][2 * p + 1], Qh[ks][1], cc0[2], cc0[3]);
                mma16816(E[0][2 * p + 2], Qh[ks][0], cc1[0], cc1[1]);
                mma16816(E[1][2 * p + 2], Qh[ks][1], cc1[0], cc1[1]);
                mma16816(E[0][2 * p + 3], Qh[ks][0], cc1[2], cc1[3]);
                mma16816(E[1][2 * p + 3], Qh[ks][1], cc1[2], cc1[3]);
                // pass 3: Qlo * Khi
                mma16816(E[0][2 * p],     Ql[ks][0], bb0[0], bb0[1]);
                mma16816(E[1][2 * p],     Ql[ks][1], bb0[0], bb0[1]);
                mma16816(E[0][2 * p + 1], Ql[ks][0], bb0[2], bb0[3]);
                mma16816(E[1][2 * p + 1], Ql[ks][1], bb0[2], bb0[3]);
                mma16816(E[0][2 * p + 2], Ql[ks][0], bb1[0], bb1[1]);
                mma16816(E[1][2 * p + 2], Ql[ks][1], bb1[0], bb1[1]);
                mma16816(E[0][2 * p + 3], Ql[ks][0], bb1[2], bb1[3]);
                mma16816(E[1][2 * p + 3], Ql[ks][1], bb1[2], bb1[3]);
            }
        }
        // ---- exp2 + sum ----
#pragma unroll
        for (int mf = 0; mf < 2; mf++)
#pragma unroll
            for (int nf = 0; nf < 8; nf++)
#pragma unroll
                for (int j = 0; j < 4; j++) {
                    float e = ex2f(E[mf][nf][j]);
                    E[mf][nf][j] = e;
                    sumE += e;
                }
        // ---- O += P @ V (3-pass; Ph passes first, Pl pack overlapped) ----
#pragma unroll
        for (int j = 0; j < 4; j++) {
            uint32_t Ph[2][4], vv[4][4], ww[4][4];
#pragma unroll
            for (int mf = 0; mf < 2; mf++) {
                float* e0 = E[mf][2 * j];
                float* e1 = E[mf][2 * j + 1];
                Ph[mf][0] = pkf(e0[0], e0[1]);
                Ph[mf][1] = pkf(e0[2], e0[3]);
                Ph[mf][2] = pkf(e1[0], e1[1]);
                Ph[mf][3] = pkf(e1[2], e1[3]);
            }
#pragma unroll
            for (int p = 0; p < 4; p++) ldsm_x4(vv[p], vh + v2_off[p] + j * 32);
#pragma unroll
            for (int p = 0; p < 4; p++) ldsm_x4(ww[p], vl + v2_off[p] + j * 32);
            // pass 1: Phi * Vhi
#pragma unroll
            for (int p = 0; p < 4; p++) {
                mma16816(O[0][2 * p],     Ph[0], vv[p][0], vv[p][1]);
                mma16816(O[1][2 * p],     Ph[1], vv[p][0], vv[p][1]);
                mma16816(O[0][2 * p + 1], Ph[0], vv[p][2], vv[p][3]);
                mma16816(O[1][2 * p + 1], Ph[1], vv[p][2], vv[p][3]);
            }
            // pass 2: Phi * Vlo (runs while Pl pack completes)
#pragma unroll
            for (int p = 0; p < 4; p++) {
                mma16816(O[0][2 * p],     Ph[0], ww[p][0], ww[p][1]);
                mma16816(O[1][2 * p],     Ph[1], ww[p][0], ww[p][1]);
                mma16816(O[0][2 * p + 1], Ph[0], ww[p][2], ww[p][3]);
                mma16816(O[1][2 * p + 1], Ph[1], ww[p][2], ww[p][3]);
            }
            // Pl residual pack
            uint32_t Pl[2][4];
#pragma unroll
            for (int mf = 0; mf < 2; mf++) {
                float* e0 = E[mf][2 * j];
                float* e1 = E[mf][2 * j + 1];
                Pl[mf][0] = pkf(e0[0] - bf_lo_as_f(Ph[mf][0]), e0[1] - bf_hi_as_f(Ph[mf][0]));
                Pl[mf][1] = pkf(e0[2] - bf_lo_as_f(Ph[mf][1]), e0[3] - bf_hi_as_f(Ph[mf][1]));
                Pl[mf][2] = pkf(e1[0] - bf_lo_as_f(Ph[mf][2]), e1[1] - bf_hi_as_f(Ph[mf][2]));
                Pl[mf][3] = pkf(e1[2] - bf_lo_as_f(Ph[mf][3]), e1[3] - bf_hi_as_f(Ph[mf][3]));
            }
            // pass 3: Plo * Vhi
#pragma unroll
            for (int p = 0; p < 4; p++) {
                mma16816(O[0][2 * p],     Pl[0], vv[p][0], vv[p][1]);
                mma16816(O[1][2 * p],     Pl[1], vv[p][0], vv[p][1]);
                mma16816(O[0][2 * p + 1], Pl[0], vv[p][2], vv[p][3]);
                mma16816(O[1][2 * p + 1], Pl[1], vv[p][2], vv[p][3]);
            }
        }
        __syncthreads();
    }

    // ---- exp-sum reduction ----
#pragma unroll
    for (int off = 16; off > 0; off >>= 1)
        sumE += __shfl_xor_sync(0xffffffffu, sumE, off);
    if (lid == 0) atomicAdd(&ssum, sumE);

    // ---- O reduction across the two n-warp halves + fp32 store ----
    float* Obuf = (float*)(smem + KBASE);
    if (wid >= 4) {
#pragma unroll
        for (int mf = 0; mf < 2; mf++) {
            int r = wm + mf * 16 + g;
#pragma unroll
            for (int nf = 0; nf < 8; nf++) {
                int c = nf * 8 + t2;
                *(float2*)(Obuf + r * HD + c) = make_float2(O[mf][nf][0], O[mf][nf][1]);
                *(float2*)(Obuf + (r + 8) * HD + c) = make_float2(O[mf][nf][2], O[mf][nf][3]);
            }
        }
    }
    __syncthreads();
    if (tid == 0) atomicAdd(&g_sum[h], ssum);
    if (wid < 4) {
#pragma unroll
        for (int mf = 0; mf < 2; mf++) {
            int r = wm + mf * 16 + g;
#pragma unroll
            for (int nf = 0; nf < 8; nf++) {
                int c = nf * 8 + t2;
                float2 p0 = *(float2*)(Obuf + r * HD + c);
                float2 p1 = *(float2*)(Obuf + (r + 8) * HD + c);
                *(float2*)(Oglob + (size_t)(m0 + r) * DIM + h * HD + c) =
                    make_float2(O[mf][nf][0] + p0.x, O[mf][nf][1] + p0.y);
                *(float2*)(Oglob + (size_t)(m0 + r + 8) * DIM + h * HD + c) =
                    make_float2(O[mf][nf][2] + p1.x, O[mf][nf][3] + p1.y);
            }
        }
    }
}

// combine the two KV splits, normalize by per-head exp-sum, split to bf16 planes
__global__ void __launch_bounds__(256) scale_split() {
    __shared__ float inv[NH];
    if (threadIdx.x < NH) inv[threadIdx.x] = 1.0f / g_sum[threadIdx.x];
    __syncthreads();
    size_t i = (size_t)blockIdx.x * 256 + threadIdx.x;
    float4 v = ((const float4*)g_attn)[i];
    float4 w = ((const float4*)g_attn2)[i];
    int col = (int)((i * 4) & (DIM - 1));
    float s = inv[col >> 6];
    v.x = (v.x + w.x) * s; v.y = (v.y + w.y) * s;
    v.z = (v.z + w.z) * s; v.w = (v.w + w.w) * s;
    uint32_t h0 = pkf(v.x, v.y), h1 = pkf(v.z, v.w);
    uint32_t l0 = pkf(v.x - bf_lo_as_f(h0), v.y - bf_hi_as_f(h0));
    uint32_t l1 = pkf(v.z - bf_lo_as_f(h1), v.w - bf_hi_as_f(h1));
    ((uint2*)g_at_hi)[i] = make_uint2(h0, h1);
    ((uint2*)g_at_lo)[i] = make_uint2(l0, l1);
}

// ---------------- launch ----------------
extern "C" void kernel_launch(void* const* d_in, const int* in_sizes, int n_in,
                              void* d_out, int out_size)
{
    const float* x = (const float*)d_in[0];
    const float* W_in = (const float*)d_in[1];
    const float* W_out = (const float*)d_in[2];
    float* out = (float*)d_out;

    __nv_bfloat16 *xs_hi, *xs_lo, *wi_hi, *wi_lo, *wo_hi, *wo_lo;
    __nv_bfloat16 *qkv_hi, *qkv_lo, *at_hi, *at_lo;
    cudaGetSymbolAddress((void**)&xs_hi, g_xs_hi);
    cudaGetSymbolAddress((void**)&xs_lo, g_xs_lo);
    cudaGetSymbolAddress((void**)&wi_hi, g_wi_hi);
    cudaGetSymbolAddress((void**)&wi_lo, g_wi_lo);
    cudaGetSymbolAddress((void**)&wo_hi, g_wo_hi);
    cudaGetSymbolAddress((void**)&wo_lo, g_wo_lo);
    cudaGetSymbolAddress((void**)&qkv_hi, g_qkv_hi);
    cudaGetSymbolAddress((void**)&qkv_lo, g_qkv_lo);
    cudaGetSymbolAddress((void**)&at_hi, g_at_hi);
    cudaGetSymbolAddress((void**)&at_lo, g_at_lo);

    const int SMEMG = 2 * (2 * 64 * PAD * 2 + 2 * 128 * PAD * 2);  // 110592
    const int SMEMF = 2 * 128 * PAD * 2 + 2 * (2 * 128 * PAD * 2)
                    + 2 * (2 * 64 * PADV * 2);                     // 180224
    cudaFuncSetAttribute(gemm_bf16<true>,
                         cudaFuncAttributeMaxDynamicSharedMemorySize, SMEMG);
    cudaFuncSetAttribute(gemm_bf16<false>,
                         cudaFuncAttributeMaxDynamicSharedMemorySize, SMEMG);
    cudaFuncSetAttribute(flash_attn,
                         cudaFuncAttributeMaxDynamicSharedMemorySize, SMEMF);

    init_kernel<<<1, 32>>>();

    // split inputs into bf16 hi/lo planes
    split_f32<<<(TLEN * DIM / 4 + 255) / 256, 256>>>(x, xs_hi, xs_lo, TLEN * DIM / 4);
    split_f32<<<(QKV_N * DIM / 4 + 255) / 256, 256>>>(W_in, wi_hi, wi_lo, QKV_N * DIM / 4);
    split_f32<<<(DIM * DIM / 4 + 255) / 256, 256>>>(W_out, wo_hi, wo_lo, DIM * DIM / 4);

    // qkv = x @ W_in^T ; q pre-scaled by 0.125*log2e; split planes out
    gemm_bf16<true><<<dim3(QKV_N / 128, TLEN / 64), 256, SMEMG>>>(
        xs_hi, xs_lo, DIM, wi_hi, wi_lo, DIM,
        nullptr, qkv_hi, qkv_lo, QKV_N, DIM, DIM);

    // V^T per head (both planes)
    transpose_v<<<dim3(TLEN / 64, NH), 256>>>();

    // fused attention, KV split x2 -> two unnormalized fp32 partials + exp-sums
    flash_attn<<<dim3(TLEN / 128, NH, 2), 256, SMEMF>>>();

    // combine splits, normalize, split to bf16 planes
    scale_split<<<TLEN * DIM / 4 / 256, 256>>>();

    // out = attn @ W_out^T
    gemm_bf16<false><<<dim3(DIM / 128, TLEN / 64), 256, SMEMG>>>(
        at_hi, at_lo, DIM, wo_hi, wo_lo, DIM,
        out, nullptr, nullptr, DIM, DIM, 0);
}

// round 15
// speedup vs baseline: 1.0063x; 1.0063x over previous
#include <cuda_runtime.h>
#include <cuda_bf16.h>
#include <cstdint>

#define TLEN 4096
#define DIM 1024
#define NH 16
#define HD 64
#define QKV_N 3072
#define PAD 72      // bf16 elems per smem row (144 B)
#define PADV 136    // bf16 elems per smem row for V^T tiles (272 B)
#define QSCALE 0.18033688011112042f   // 0.125 * log2(e)

// ---------------- scratch (allocation-free) ----------------
__device__ __nv_bfloat16 g_xs_hi[(size_t)TLEN * DIM],  g_xs_lo[(size_t)TLEN * DIM];
__device__ __nv_bfloat16 g_wi_hi[(size_t)QKV_N * DIM], g_wi_lo[(size_t)QKV_N * DIM];
__device__ __nv_bfloat16 g_wo_hi[(size_t)DIM * DIM],   g_wo_lo[(size_t)DIM * DIM];
__device__ __nv_bfloat16 g_qkv_hi[(size_t)TLEN * QKV_N], g_qkv_lo[(size_t)TLEN * QKV_N];
__device__ __nv_bfloat16 g_vt_hi[(size_t)NH * HD * TLEN], g_vt_lo[(size_t)NH * HD * TLEN];
__device__ __nv_bfloat16 g_at_hi[(size_t)TLEN * DIM],  g_at_lo[(size_t)TLEN * DIM];
__device__ float g_attn[(size_t)TLEN * DIM];
__device__ float g_attn2[(size_t)TLEN * DIM];
__device__ float g_sum[NH];

// ---------------- helpers ----------------
__device__ __forceinline__ uint32_t smem_u32(const void* p) {
    uint32_t a;
    asm("{ .reg .u64 t; cvta.to.shared.u64 t, %1; cvt.u32.u64 %0, t; }" : "=r"(a) : "l"(p));
    return a;
}
__device__ __forceinline__ uint32_t pkf(float a, float b) {
    uint32_t r;
    asm("cvt.rn.bf16x2.f32 %0, %1, %2;" : "=r"(r) : "f"(b), "f"(a));
    return r;
}
__device__ __forceinline__ float bf_lo_as_f(uint32_t u) { return __uint_as_float(u << 16); }
__device__ __forceinline__ float bf_hi_as_f(uint32_t u) { return __uint_as_float(u & 0xffff0000u); }
__device__ __forceinline__ float ex2f(float x) {
    float y;
    asm("ex2.approx.f32 %0, %1;" : "=f"(y) : "f"(x));
    return y;
}

__device__ __forceinline__ void ldsm_x4(uint32_t* r, uint32_t addr) {
    asm volatile("ldmatrix.sync.aligned.m8n8.x4.shared.b16 {%0,%1,%2,%3}, [%4];"
                 : "=r"(r[0]), "=r"(r[1]), "=r"(r[2]), "=r"(r[3]) : "r"(addr));
}
__device__ __forceinline__ void mma16816(float* c, const uint32_t* a, uint32_t b0, uint32_t b1) {
    asm volatile(
        "mma.sync.aligned.m16n8k16.row.col.f32.bf16.bf16.f32 "
        "{%0,%1,%2,%3}, {%4,%5,%6,%7}, {%8,%9}, {%0,%1,%2,%3};"
        : "+f"(c[0]), "+f"(c[1]), "+f"(c[2]), "+f"(c[3])
        : "r"(a[0]), "r"(a[1]), "r"(a[2]), "r"(a[3]), "r"(b0), "r"(b1));
}
__device__ __forceinline__ void cp16(uint32_t dst, const void* src) {
    asm volatile("cp.async.cg.shared.global [%0], [%1], 16;" :: "r"(dst), "l"(src));
}
#define CP_COMMIT() asm volatile("cp.async.commit_group;" ::: "memory")
#define CP_WAIT(N)  asm volatile("cp.async.wait_group %0;" :: "n"(N) : "memory")

__global__ void init_kernel() {
    if (threadIdx.x < NH) g_sum[threadIdx.x] = 0.0f;
}

// fp32 -> split bf16 hi/lo planes
__global__ void __launch_bounds__(256) split_f32(const float* __restrict__ src,
                                                 __nv_bfloat16* __restrict__ hi,
                                                 __nv_bfloat16* __restrict__ lo, int n4) {
    int i = blockIdx.x * 256 + threadIdx.x;
    if (i >= n4) return;
    float4 v = ((const float4*)src)[i];
    uint32_t h0 = pkf(v.x, v.y), h1 = pkf(v.z, v.w);
    uint32_t l0 = pkf(v.x - bf_lo_as_f(h0), v.y - bf_hi_as_f(h0));
    uint32_t l1 = pkf(v.z - bf_lo_as_f(h1), v.w - bf_hi_as_f(h1));
    ((uint2*)hi)[i] = make_uint2(h0, h1);
    ((uint2*)lo)[i] = make_uint2(l0, l1);
}

// V^T per head: vt[h][d][s] = V[s][d], both planes
__global__ void __launch_bounds__(256) transpose_v() {
    __shared__ ushort th[64][65], tl[64][65];
    int h = blockIdx.y, s0 = blockIdx.x * 64;
    int tid = threadIdx.x;
#pragma unroll
    for (int i = 0; i < 16; i++) {
        int slot = tid + i * 256;
        int s = slot >> 6, d = slot & 63;
        size_t src = (size_t)(s0 + s) * QKV_N + 2 * DIM + h * HD + d;
        th[s][d] = ((const ushort*)g_qkv_hi)[src];
        tl[s][d] = ((const ushort*)g_qkv_lo)[src];
    }
    __syncthreads();
#pragma unroll
    for (int i = 0; i < 16; i++) {
        int slot = tid + i * 256;
        int d = slot >> 6, s = slot & 63;
        size_t dst = ((size_t)h * HD + d) * TLEN + s0 + s;
        ((ushort*)g_vt_hi)[dst] = th[s][d];
        ((ushort*)g_vt_lo)[dst] = tl[s][d];
    }
}

// ---------------- split-bf16 3-pass GEMM: 64x128 tile, 2 CTAs/SM (untouched) ----------------
template <bool SPLIT_OUT>
__global__ void __launch_bounds__(256, 2) gemm_bf16(
    const __nv_bfloat16* __restrict__ Ahi, const __nv_bfloat16* __restrict__ Alo, int lda,
    const __nv_bfloat16* __restrict__ Bhi, const __nv_bfloat16* __restrict__ Blo, int ldb,
    float* __restrict__ Cf, __nv_bfloat16* __restrict__ Chi, __nv_bfloat16* __restrict__ Clo,
    int ldc, int K, int qcols)
{
    extern __shared__ char smem[];
    uint32_t su = smem_u32(smem);
    constexpr uint32_t PLA = 64 * PAD * 2;
    constexpr uint32_t PLB = 128 * PAD * 2;
    constexpr uint32_t STG = 2 * PLA + 2 * PLB;

    int m0 = blockIdx.y * 64, n0 = blockIdx.x * 128;
    int tid = threadIdx.x, wid = tid >> 5, lid = tid & 31;
    int wm = (wid & 1) * 32, wn = (wid >> 1) * 32;
    int g = lid >> 2, t2 = (lid & 3) * 2, rsel = lid & 7, mat = lid >> 3;

    uint32_t a_off[2], b2_off[2];
#pragma unroll
    for (int mf = 0; mf < 2; mf++)
        a_off[mf] = (uint32_t)(((wm + mf * 16 + (mat & 1) * 8 + rsel) * PAD + (mat >> 1) * 8) * 2);
#pragma unroll
    for (int p = 0; p < 2; p++)
        b2_off[p] = (uint32_t)(((wn + p * 16 + (mat >> 1) * 8 + rsel) * PAD + (mat & 1) * 8) * 2);

    auto issue = [&](int kc, int st) {
        uint32_t base = su + st * STG;
        int k0 = kc * 64;
#pragma unroll
        for (int i = 0; i < 2; i++) {
            int idx = tid + i * 256;
            int row = idx >> 3, ch = idx & 7;
            uint32_t d = base + (uint32_t)((row * PAD + ch * 8) * 2);
            cp16(d,       Ahi + (size_t)(m0 + row) * lda + k0 + ch * 8);
            cp16(d + PLA, Alo + (size_t)(m0 + row) * lda + k0 + ch * 8);
        }
#pragma unroll
        for (int i = 0; i < 4; i++) {
            int idx = tid + i * 256;
            int row = idx >> 3, ch = idx & 7;
            uint32_t d = base + 2 * PLA + (uint32_t)((row * PAD + ch * 8) * 2);
            cp16(d,       Bhi + (size_t)(n0 + row) * ldb + k0 + ch * 8);
            cp16(d + PLB, Blo + (size_t)(n0 + row) * ldb + k0 + ch * 8);
        }
        CP_COMMIT();
    };

    float acc[2][4][4];
#pragma unroll
    for (int mf = 0; mf < 2; mf++)
#pragma unroll
        for (int nf = 0; nf < 4; nf++)
#pragma unroll
            for (int j = 0; j < 4; j++) acc[mf][nf][j] = 0.0f;

    int NKC = K / 64;
    issue(0, 0);
    for (int kc = 0; kc < NKC; kc++) {
        int st = kc & 1;
        if (kc + 1 < NKC) { issue(kc + 1, st ^ 1); CP_WAIT(1); }
        else              { CP_WAIT(0); }
        __syncthreads();
        uint32_t ah = su + st * STG, al = ah + PLA;
        uint32_t bh = su + st * STG + 2 * PLA, bl = bh + PLB;
#pragma unroll
        for (int ks = 0; ks < 4; ks++) {
            uint32_t kb = (uint32_t)(ks * 32);
            uint32_t fh[2][4], fl[2][4];
            ldsm_x4(fh[0], ah + a_off[0] + kb);
            ldsm_x4(fh[1], ah + a_off[1] + kb);
            ldsm_x4(fl[0], al + a_off[0] + kb);
            ldsm_x4(fl[1], al + a_off[1] + kb);
#pragma unroll
            for (int p = 0; p < 2; p++) {
                uint32_t bb[4], cc[4];
                ldsm_x4(bb, bh + b2_off[p] + kb);
                mma16816(acc[0][2 * p],     fh[0], bb[0], bb[1]);
                mma16816(acc[1][2 * p],     fh[1], bb[0], bb[1]);
                mma16816(acc[0][2 * p + 1], fh[0], bb[2], bb[3]);
                mma16816(acc[1][2 * p + 1], fh[1], bb[2], bb[3]);
                mma16816(acc[0][2 * p],     fl[0], bb[0], bb[1]);
                mma16816(acc[1][2 * p],     fl[1], bb[0], bb[1]);
                mma16816(acc[0][2 * p + 1], fl[0], bb[2], bb[3]);
                mma16816(acc[1][2 * p + 1], fl[1], bb[2], bb[3]);
                ldsm_x4(cc, bl + b2_off[p] + kb);
                mma16816(acc[0][2 * p],     fh[0], cc[0], cc[1]);
                mma16816(acc[1][2 * p],     fh[1], cc[0], cc[1]);
                mma16816(acc[0][2 * p + 1], fh[0], cc[2], cc[3]);
                mma16816(acc[1][2 * p + 1], fh[1], cc[2], cc[3]);
            }
        }
        __syncthreads();
    }

    // epilogue
#pragma unroll
    for (int mf = 0; mf < 2; mf++) {
        int r0 = m0 + wm + mf * 16 + g;
#pragma unroll
        for (int nf = 0; nf < 4; nf++) {
            int col = n0 + wn + nf * 8 + t2;
            float sc = 1.0f;
            if (SPLIT_OUT && col < qcols) sc = QSCALE;
            float v0 = acc[mf][nf][0] * sc, v1 = acc[mf][nf][1] * sc;
            float v2 = acc[mf][nf][2] * sc, v3 = acc[mf][nf][3] * sc;
            if (SPLIT_OUT) {
                uint32_t h0 = pkf(v0, v1);
                uint32_t l0 = pkf(v0 - bf_lo_as_f(h0), v1 - bf_hi_as_f(h0));
                *(uint32_t*)(Chi + (size_t)r0 * ldc + col) = h0;
                *(uint32_t*)(Clo + (size_t)r0 * ldc + col) = l0;
                uint32_t h1 = pkf(v2, v3);
                uint32_t l1 = pkf(v2 - bf_lo_as_f(h1), v3 - bf_hi_as_f(h1));
                *(uint32_t*)(Chi + (size_t)(r0 + 8) * ldc + col) = h1;
                *(uint32_t*)(Clo + (size_t)(r0 + 8) * ldc + col) = l1;
            } else {
                *(float2*)(Cf + (size_t)r0 * ldc + col) = make_float2(v0, v1);
                *(float2*)(Cf + (size_t)(r0 + 8) * ldc + col) = make_float2(v2, v3);
            }
        }
    }
}

// ---------------- fused attention (exp interleaved into PV, 4-way sum partials) ----------------
__global__ void __launch_bounds__(256) flash_attn()
{
    extern __shared__ char smem[];
    __shared__ float ssum;
    uint32_t su = smem_u32(smem);
    constexpr uint32_t QLO   = 128 * PAD * 2;
    constexpr uint32_t KBASE = 2 * 128 * PAD * 2;
    constexpr uint32_t KSTG  = 2 * 128 * PAD * 2;
    constexpr uint32_t VBASE = KBASE + 2 * KSTG;
    constexpr uint32_t VPL   = 64 * PADV * 2;
    constexpr uint32_t VSTG  = 2 * VPL;
    constexpr int NSPLIT_T = (TLEN / 128) / 2;   // 16 key tiles per split

    int h = blockIdx.y;
    int m0 = blockIdx.x * 128;
    int z = blockIdx.z;
    int tbase = z * NSPLIT_T;
    float* Oglob = z ? g_attn2 : g_attn;
    int tid = threadIdx.x, wid = tid >> 5, lid = tid & 31;
    int wm = (wid & 3) * 32, wn = (wid >> 2) * 64;
    int g = lid >> 2, t2 = (lid & 3) * 2, rsel = lid & 7, mat = lid >> 3;

    // load Q tile planes (pre-scaled by 0.125*log2e)
#pragma unroll
    for (int i = 0; i < 4; i++) {
        int idx = tid + i * 256;
        int row = idx >> 3, ch = idx & 7;
        size_t src = (size_t)(m0 + row) * QKV_N + h * HD + ch * 8;
        uint32_t d = (uint32_t)((row * PAD + ch * 8) * 2);
        *(uint4*)(smem + d)       = *(const uint4*)(g_qkv_hi + src);
        *(uint4*)(smem + QLO + d) = *(const uint4*)(g_qkv_lo + src);
    }
    if (tid == 0) ssum = 0.0f;

    uint32_t a_off[2], b2_off[4], v2_off[4];
#pragma unroll
    for (int mf = 0; mf < 2; mf++)
        a_off[mf] = (uint32_t)(((wm + mf * 16 + (mat & 1) * 8 + rsel) * PAD + (mat >> 1) * 8) * 2);
#pragma unroll
    for (int p = 0; p < 4; p++) {
        b2_off[p] = (uint32_t)(((wn + p * 16 + (mat >> 1) * 8 + rsel) * PAD + (mat & 1) * 8) * 2);
        v2_off[p] = (uint32_t)(((p * 16 + (mat >> 1) * 8 + rsel) * PADV + wn + (mat & 1) * 8) * 2);
    }

    auto issue = [&](int t, int st) {
        int s0 = t * 128;
        uint32_t kb = su + KBASE + st * KSTG;
#pragma unroll
        for (int i = 0; i < 4; i++) {
            int idx = tid + i * 256;
            int row = idx >> 3, ch = idx & 7;
            size_t src = (size_t)(s0 + row) * QKV_N + DIM + h * HD + ch * 8;
            uint32_t d = kb + (uint32_t)((row * PAD + ch * 8) * 2);
            cp16(d,                 g_qkv_hi + src);
            cp16(d + 128 * PAD * 2, g_qkv_lo + src);
        }
        uint32_t vb = su + VBASE + st * VSTG;
#pragma unroll
        for (int i = 0; i < 4; i++) {
            int idx = tid + i * 256;
            int dd = idx >> 4, ch = idx & 15;
            size_t src = ((size_t)h * HD + dd) * TLEN + s0 + ch * 8;
            uint32_t d = vb + (uint32_t)((dd * PADV + ch * 8) * 2);
            cp16(d,       g_vt_hi + src);
            cp16(d + VPL, g_vt_lo + src);
        }
        CP_COMMIT();
    };

    issue(tbase, 0);
    __syncthreads();

    // hoist Q-hi fragments (invariant over key tiles)
    uint32_t Qh[4][2][4];
#pragma unroll
    for (int ks = 0; ks < 4; ks++)
#pragma unroll
        for (int mf = 0; mf < 2; mf++)
            ldsm_x4(Qh[ks][mf], su + a_off[mf] + ks * 32);

    float O[2][8][4];
#pragma unroll
    for (int mf = 0; mf < 2; mf++)
#pragma unroll
        for (int nf = 0; nf < 8; nf++)
#pragma unroll
            for (int j = 0; j < 4; j++) O[mf][nf][j] = 0.0f;
    float sE[4] = {0.0f, 0.0f, 0.0f, 0.0f};

    for (int tt = 0; tt < NSPLIT_T; tt++) {
        int st = tt & 1;
        if (tt + 1 < NSPLIT_T) { issue(tbase + tt + 1, st ^ 1); CP_WAIT(1); }
        else                   { CP_WAIT(0); }
        __syncthreads();

        uint32_t ql = su + QLO;
        uint32_t kh = su + KBASE + st * KSTG, kl = kh + 128 * PAD * 2;
        uint32_t vh = su + VBASE + st * VSTG, vl = vh + VPL;

        // ---- S = Q @ K^T (3-pass; Q-lo loaded once per ks) ----
        float E[2][8][4];
#pragma unroll
        for (int mf = 0; mf < 2; mf++)
#pragma unroll
            for (int nf = 0; nf < 8; nf++)
#pragma unroll
                for (int j = 0; j < 4; j++) E[mf][nf][j] = 0.0f;
#pragma unroll
        for (int ks = 0; ks < 4; ks++) {
            uint32_t kb = (uint32_t)(ks * 32);
            uint32_t fl[2][4];
            ldsm_x4(fl[0], ql + a_off[0] + kb);
            ldsm_x4(fl[1], ql + a_off[1] + kb);
#pragma unroll
            for (int p = 0; p < 4; p += 2) {
                uint32_t bb0[4], bb1[4], cc0[4], cc1[4];
                ldsm_x4(bb0, kh + b2_off[p] + kb);
                ldsm_x4(bb1, kh + b2_off[p + 1] + kb);
                ldsm_x4(cc0, kl + b2_off[p] + kb);
                ldsm_x4(cc1, kl + b2_off[p + 1] + kb);
                // pass 1: Qhi * Khi
                mma16816(E[0][2 * p],     Qh[ks][0], bb0[0], bb0[1]);
                mma16816(E[1][2 * p],     Qh[ks][1], bb0[0], bb0[1]);
                mma16816(E[0][2 * p + 1], Qh[ks][0], bb0[2], bb0[3]);
                mma16816(E[1][2 * p + 1], Qh[ks][1], bb0[2], bb0[3]);
                mma16816(E[0][2 * p + 2], Qh[ks][0], bb1[0], bb1[1]);
                mma16816(E[1][2 * p + 2], Qh[ks][1], bb1[0], bb1[1]);
                mma16816(E[0][2 * p + 3], Qh[ks][0], bb1[2], bb1[3]);
                mma16816(E[1][2 * p + 3], Qh[ks][1], bb1[2], bb1[3]);
                // pass 2: Qhi * Klo
                mma16816(E[0][2 * p],     Qh[ks][0], cc0[0], cc0[1]);
                mma16816(E[1][2 * p],     Qh[ks][1], cc0[0], cc0[1]);
                mma16816(E[0][2 * p + 1], Qh[ks][0], cc0[2], cc0[3]);
                mma16816(E[1][2 * p + 1], Qh[ks][1], cc0[2], cc0[3]);
                mma16816(E[0][2 * p + 2], Qh[ks][0], cc1[0], cc1[1]);
                mma16816(E[1][2 * p + 2], Qh[ks][1], cc1[0], cc1[1]);
                mma16816(E[0][2 * p + 3], Qh[ks][0], cc1[2], cc1[3]);
                mma16816(E[1][2 * p + 3], Qh[ks][1], cc1[2], cc1[3]);
                // pass 3: Qlo * Khi
                mma16816(E[0][2 * p],     fl[0], bb0[0], bb0[1]);
                mma16816(E[1][2 * p],     fl[1], bb0[0], bb0[1]);
                mma16816(E[0][2 * p + 1], fl[0], bb0[2], bb0[3]);
                mma16816(E[1][2 * p + 1], fl[1], bb0[2], bb0[3]);
                mma16816(E[0][2 * p + 2], fl[0], bb1[0], bb1[1]);
                mma16816(E[1][2 * p + 2], fl[1], bb1[0], bb1[1]);
                mma16816(E[0][2 * p + 3], fl[0], bb1[2], bb1[3]);
                mma16816(E[1][2 * p + 3], fl[1], bb1[2], bb1[3]);
            }
        }
        // ---- PV with per-j exp2 + partial sums (overlaps MUFU with tensor pipe) ----
#pragma unroll
        for (int j = 0; j < 4; j++) {
            // exp2 only this j's 16 values; private partial accumulator
            float s = 0.0f;
#pragma unroll
            for (int mf = 0; mf < 2; mf++)
#pragma unroll
                for (int q = 0; q < 2; q++)
#pragma unroll
                    for (int jj = 0; jj < 4; jj++) {
                        float e = ex2f(E[mf][2 * j + q][jj]);
                        E[mf][2 * j + q][jj] = e;
                        s += e;
                    }
            sE[j] += s;

            uint32_t Ph[2][4], vv[4][4], ww[4][4];
#pragma unroll
            for (int mf = 0; mf < 2; mf++) {
                float* e0 = E[mf][2 * j];
                float* e1 = E[mf][2 * j + 1];
                Ph[mf][0] = pkf(e0[0], e0[1]);
                Ph[mf][1] = pkf(e0[2], e0[3]);
                Ph[mf][2] = pkf(e1[0], e1[1]);
                Ph[mf][3] = pkf(e1[2], e1[3]);
            }
#pragma unroll
            for (int p = 0; p < 4; p++) ldsm_x4(vv[p], vh + v2_off[p] + j * 32);
#pragma unroll
            for (int p = 0; p < 4; p++) ldsm_x4(ww[p], vl + v2_off[p] + j * 32);
            // pass 1: Phi * Vhi
#pragma unroll
            for (int p = 0; p < 4; p++) {
                mma16816(O[0][2 * p],     Ph[0], vv[p][0], vv[p][1]);
                mma16816(O[1][2 * p],     Ph[1], vv[p][0], vv[p][1]);
                mma16816(O[0][2 * p + 1], Ph[0], vv[p][2], vv[p][3]);
                mma16816(O[1][2 * p + 1], Ph[1], vv[p][2], vv[p][3]);
            }
            // pass 2: Phi * Vlo (Pl pack overlaps)
#pragma unroll
            for (int p = 0; p < 4; p++) {
                mma16816(O[0][2 * p],     Ph[0], ww[p][0], ww[p][1]);
                mma16816(O[1][2 * p],     Ph[1], ww[p][0], ww[p][1]);
                mma16816(O[0][2 * p + 1], Ph[0], ww[p][2], ww[p][3]);
                mma16816(O[1][2 * p + 1], Ph[1], ww[p][2], ww[p][3]);
            }
            // Pl residual pack
            uint32_t Pl[2][4];
#pragma unroll
            for (int mf = 0; mf < 2; mf++) {
                float* e0 = E[mf][2 * j];
                float* e1 = E[mf][2 * j + 1];
                Pl[mf][0] = pkf(e0[0] - bf_lo_as_f(Ph[mf][0]), e0[1] - bf_hi_as_f(Ph[mf][0]));
                Pl[mf][1] = pkf(e0[2] - bf_lo_as_f(Ph[mf][1]), e0[3] - bf_hi_as_f(Ph[mf][1]));
                Pl[mf][2] = pkf(e1[0] - bf_lo_as_f(Ph[mf][2]), e1[1] - bf_hi_as_f(Ph[mf][2]));
                Pl[mf][3] = pkf(e1[2] - bf_lo_as_f(Ph[mf][3]), e1[3] - bf_hi_as_f(Ph[mf][3]));
            }
            // pass 3: Plo * Vhi
#pragma unroll
            for (int p = 0; p < 4; p++) {
                mma16816(O[0][2 * p],     Pl[0], vv[p][0], vv[p][1]);
                mma16816(O[1][2 * p],     Pl[1], vv[p][0], vv[p][1]);
                mma16816(O[0][2 * p + 1], Pl[0], vv[p][2], vv[p][3]);
                mma16816(O[1][2 * p + 1], Pl[1], vv[p][2], vv[p][3]);
            }
        }
        __syncthreads();
    }

    // ---- exp-sum reduction ----
    float sumE = (sE[0] + sE[1]) + (sE[2] + sE[3]);
#pragma unroll
    for (int off = 16; off > 0; off >>= 1)
        sumE += __shfl_xor_sync(0xffffffffu, sumE, off);
    if (lid == 0) atomicAdd(&ssum, sumE);

    // ---- O reduction across the two n-warp halves + fp32 store ----
    float* Obuf = (float*)(smem + KBASE);
    if (wid >= 4) {
#pragma unroll
        for (int mf = 0; mf < 2; mf++) {
            int r = wm + mf * 16 + g;
#pragma unroll
            for (int nf = 0; nf < 8; nf++) {
                int c = nf * 8 + t2;
                *(float2*)(Obuf + r * HD + c) = make_float2(O[mf][nf][0], O[mf][nf][1]);
                *(float2*)(Obuf + (r + 8) * HD + c) = make_float2(O[mf][nf][2], O[mf][nf][3]);
            }
        }
    }
    __syncthreads();
    if (tid == 0) atomicAdd(&g_sum[h], ssum);
    if (wid < 4) {
#pragma unroll
        for (int mf = 0; mf < 2; mf++) {
            int r = wm + mf * 16 + g;
#pragma unroll
            for (int nf = 0; nf < 8; nf++) {
                int c = nf * 8 + t2;
                float2 p0 = *(float2*)(Obuf + r * HD + c);
                float2 p1 = *(float2*)(Obuf + (r + 8) * HD + c);
                *(float2*)(Oglob + (size_t)(m0 + r) * DIM + h * HD + c) =
                    make_float2(O[mf][nf][0] + p0.x, O[mf][nf][1] + p0.y);
                *(float2*)(Oglob + (size_t)(m0 + r + 8) * DIM + h * HD + c) =
                    make_float2(O[mf][nf][2] + p1.x, O[mf][nf][3] + p1.y);
            }
        }
    }
}

// combine the two KV splits, normalize by per-head exp-sum, split to bf16 planes
__global__ void __launch_bounds__(256) scale_split() {
    __shared__ float inv[NH];
    if (threadIdx.x < NH) inv[threadIdx.x] = 1.0f / g_sum[threadIdx.x];
    __syncthreads();
    size_t i = (size_t)blockIdx.x * 256 + threadIdx.x;
    float4 v = ((const float4*)g_attn)[i];
    float4 w = ((const float4*)g_attn2)[i];
    int col = (int)((i * 4) & (DIM - 1));
    float s = inv[col >> 6];
    v.x = (v.x + w.x) * s; v.y = (v.y + w.y) * s;
    v.z = (v.z + w.z) * s; v.w = (v.w + w.w) * s;
    uint32_t h0 = pkf(v.x, v.y), h1 = pkf(v.z, v.w);
    uint32_t l0 = pkf(v.x - bf_lo_as_f(h0), v.y - bf_hi_as_f(h0));
    uint32_t l1 = pkf(v.z - bf_lo_as_f(h1), v.w - bf_hi_as_f(h1));
    ((uint2*)g_at_hi)[i] = make_uint2(h0, h1);
    ((uint2*)g_at_lo)[i] = make_uint2(l0, l1);
}

// ---------------- launch ----------------
extern "C" void kernel_launch(void* const* d_in, const int* in_sizes, int n_in,
                              void* d_out, int out_size)
{
    const float* x = (const float*)d_in[0];
    const float* W_in = (const float*)d_in[1];
    const float* W_out = (const float*)d_in[2];
    float* out = (float*)d_out;

    __nv_bfloat16 *xs_hi, *xs_lo, *wi_hi, *wi_lo, *wo_hi, *wo_lo;
    __nv_bfloat16 *qkv_hi, *qkv_lo, *at_hi, *at_lo;
    cudaGetSymbolAddress((void**)&xs_hi, g_xs_hi);
    cudaGetSymbolAddress((void**)&xs_lo, g_xs_lo);
    cudaGetSymbolAddress((void**)&wi_hi, g_wi_hi);
    cudaGetSymbolAddress((void**)&wi_lo, g_wi_lo);
    cudaGetSymbolAddress((void**)&wo_hi, g_wo_hi);
    cudaGetSymbolAddress((void**)&wo_lo, g_wo_lo);
    cudaGetSymbolAddress((void**)&qkv_hi, g_qkv_hi);
    cudaGetSymbolAddress((void**)&qkv_lo, g_qkv_lo);
    cudaGetSymbolAddress((void**)&at_hi, g_at_hi);
    cudaGetSymbolAddress((void**)&at_lo, g_at_lo);

    const int SMEMG = 2 * (2 * 64 * PAD * 2 + 2 * 128 * PAD * 2);  // 110592
    const int SMEMF = 2 * 128 * PAD * 2 + 2 * (2 * 128 * PAD * 2)
                    + 2 * (2 * 64 * PADV * 2);                     // 180224
    cudaFuncSetAttribute(gemm_bf16<true>,
                         cudaFuncAttributeMaxDynamicSharedMemorySize, SMEMG);
    cudaFuncSetAttribute(gemm_bf16<false>,
                         cudaFuncAttributeMaxDynamicSharedMemorySize, SMEMG);
    cudaFuncSetAttribute(flash_attn,
                         cudaFuncAttributeMaxDynamicSharedMemorySize, SMEMF);

    init_kernel<<<1, 32>>>();

    // split inputs into bf16 hi/lo planes
    split_f32<<<(TLEN * DIM / 4 + 255) / 256, 256>>>(x, xs_hi, xs_lo, TLEN * DIM / 4);
    split_f32<<<(QKV_N * DIM / 4 + 255) / 256, 256>>>(W_in, wi_hi, wi_lo, QKV_N * DIM / 4);
    split_f32<<<(DIM * DIM / 4 + 255) / 256, 256>>>(W_out, wo_hi, wo_lo, DIM * DIM / 4);

    // qkv = x @ W_in^T ; q pre-scaled by 0.125*log2e; split planes out
    gemm_bf16<true><<<dim3(QKV_N / 128, TLEN / 64), 256, SMEMG>>>(
        xs_hi, xs_lo, DIM, wi_hi, wi_lo, DIM,
        nullptr, qkv_hi, qkv_lo, QKV_N, DIM, DIM);

    // V^T per head (both planes)
    transpose_v<<<dim3(TLEN / 64, NH), 256>>>();

    // fused attention, KV split x2 -> two unnormalized fp32 partials + exp-sums
    flash_attn<<<dim3(TLEN / 128, NH, 2), 256, SMEMF>>>();

    // combine splits, normalize, split to bf16 planes
    scale_split<<<TLEN * DIM / 4 / 256, 256>>>();

    // out = attn @ W_out^T
    gemm_bf16<false><<<dim3(DIM / 128, TLEN / 64), 256, SMEMG>>>(
        at_hi, at_lo, DIM, wo_hi, wo_lo, DIM,
        out, nullptr, nullptr, DIM, DIM, 0);
}

// round 16
// speedup vs baseline: 1.0289x; 1.0225x over previous
#include <cuda_runtime.h>
#include <cuda_bf16.h>
#include <cstdint>

#define TLEN 4096
#define DIM 1024
#define NH 16
#define HD 64
#define QKV_N 3072
#define PAD 72      // bf16 elems per smem row (144 B)
#define PADV 136    // bf16 elems per smem row for V^T tiles (272 B)
#define QSCALE 0.18033688011112042f   // 0.125 * log2(e)

// ---------------- scratch (allocation-free) ----------------
__device__ __nv_bfloat16 g_xs_hi[(size_t)TLEN * DIM],  g_xs_lo[(size_t)TLEN * DIM];
__device__ __nv_bfloat16 g_wi_hi[(size_t)QKV_N * DIM], g_wi_lo[(size_t)QKV_N * DIM];
__device__ __nv_bfloat16 g_wo_hi[(size_t)DIM * DIM],   g_wo_lo[(size_t)DIM * DIM];
__device__ __nv_bfloat16 g_qkv_hi[(size_t)TLEN * QKV_N], g_qkv_lo[(size_t)TLEN * QKV_N];
__device__ __nv_bfloat16 g_vt_hi[(size_t)NH * HD * TLEN], g_vt_lo[(size_t)NH * HD * TLEN];
__device__ __nv_bfloat16 g_at_hi[(size_t)TLEN * DIM],  g_at_lo[(size_t)TLEN * DIM];
__device__ float g_attn[(size_t)TLEN * DIM];
__device__ float g_attn2[(size_t)TLEN * DIM];
__device__ float g_sum[NH];

// ---------------- helpers ----------------
__device__ __forceinline__ uint32_t smem_u32(const void* p) {
    uint32_t a;
    asm("{ .reg .u64 t; cvta.to.shared.u64 t, %1; cvt.u32.u64 %0, t; }" : "=r"(a) : "l"(p));
    return a;
}
__device__ __forceinline__ uint32_t pkf(float a, float b) {
    uint32_t r;
    asm("cvt.rn.bf16x2.f32 %0, %1, %2;" : "=r"(r) : "f"(b), "f"(a));
    return r;
}
__device__ __forceinline__ float bf_lo_as_f(uint32_t u) { return __uint_as_float(u << 16); }
__device__ __forceinline__ float bf_hi_as_f(uint32_t u) { return __uint_as_float(u & 0xffff0000u); }
__device__ __forceinline__ float ex2f(float x) {
    float y;
    asm("ex2.approx.f32 %0, %1;" : "=f"(y) : "f"(x));
    return y;
}

__device__ __forceinline__ void ldsm_x4(uint32_t* r, uint32_t addr) {
    asm volatile("ldmatrix.sync.aligned.m8n8.x4.shared.b16 {%0,%1,%2,%3}, [%4];"
                 : "=r"(r[0]), "=r"(r[1]), "=r"(r[2]), "=r"(r[3]) : "r"(addr));
}
__device__ __forceinline__ void mma16816(float* c, const uint32_t* a, uint32_t b0, uint32_t b1) {
    asm volatile(
        "mma.sync.aligned.m16n8k16.row.col.f32.bf16.bf16.f32 "
        "{%0,%1,%2,%3}, {%4,%5,%6,%7}, {%8,%9}, {%0,%1,%2,%3};"
        : "+f"(c[0]), "+f"(c[1]), "+f"(c[2]), "+f"(c[3])
        : "r"(a[0]), "r"(a[1]), "r"(a[2]), "r"(a[3]), "r"(b0), "r"(b1));
}
__device__ __forceinline__ void cp16(uint32_t dst, const void* src) {
    asm volatile("cp.async.cg.shared.global [%0], [%1], 16;" :: "r"(dst), "l"(src));
}
#define CP_COMMIT() asm volatile("cp.async.commit_group;" ::: "memory")
#define CP_WAIT(N)  asm volatile("cp.async.wait_group %0;" :: "n"(N) : "memory")

__global__ void init_kernel() {
    if (threadIdx.x < NH) g_sum[threadIdx.x] = 0.0f;
}

// merged fp32 -> split bf16 hi/lo planes for x, W_in, W_out (one launch)
#define N4_X  (TLEN * DIM / 4)
#define N4_WI (QKV_N * DIM / 4)
#define N4_WO (DIM * DIM / 4)
__global__ void __launch_bounds__(256) split_all(const float* __restrict__ x,
                                                 const float* __restrict__ wi,
                                                 const float* __restrict__ wo) {
    int i = blockIdx.x * 256 + threadIdx.x;
    const float* src;
    __nv_bfloat16 *hi, *lo;
    int idx;
    if (i < N4_X) {
        src = x; hi = g_xs_hi; lo = g_xs_lo; idx = i;
    } else if (i < N4_X + N4_WI) {
        src = wi; hi = g_wi_hi; lo = g_wi_lo; idx = i - N4_X;
    } else if (i < N4_X + N4_WI + N4_WO) {
        src = wo; hi = g_wo_hi; lo = g_wo_lo; idx = i - N4_X - N4_WI;
    } else {
        return;
    }
    float4 v = ((const float4*)src)[idx];
    uint32_t h0 = pkf(v.x, v.y), h1 = pkf(v.z, v.w);
    uint32_t l0 = pkf(v.x - bf_lo_as_f(h0), v.y - bf_hi_as_f(h0));
    uint32_t l1 = pkf(v.z - bf_lo_as_f(h1), v.w - bf_hi_as_f(h1));
    ((uint2*)hi)[idx] = make_uint2(h0, h1);
    ((uint2*)lo)[idx] = make_uint2(l0, l1);
}

// V^T per head: vt[h][d][s] = V[s][d], both planes
__global__ void __launch_bounds__(256) transpose_v() {
    __shared__ ushort th[64][65], tl[64][65];
    int h = blockIdx.y, s0 = blockIdx.x * 64;
    int tid = threadIdx.x;
#pragma unroll
    for (int i = 0; i < 16; i++) {
        int slot = tid + i * 256;
        int s = slot >> 6, d = slot & 63;
        size_t src = (size_t)(s0 + s) * QKV_N + 2 * DIM + h * HD + d;
        th[s][d] = ((const ushort*)g_qkv_hi)[src];
        tl[s][d] = ((const ushort*)g_qkv_lo)[src];
    }
    __syncthreads();
#pragma unroll
    for (int i = 0; i < 16; i++) {
        int slot = tid + i * 256;
        int d = slot >> 6, s = slot & 63;
        size_t dst = ((size_t)h * HD + d) * TLEN + s0 + s;
        ((ushort*)g_vt_hi)[dst] = th[s][d];
        ((ushort*)g_vt_lo)[dst] = tl[s][d];
    }
}

// ---------------- split-bf16 3-pass GEMM: 64x128 tile, 2 CTAs/SM (untouched) ----------------
template <bool SPLIT_OUT>
__global__ void __launch_bounds__(256, 2) gemm_bf16(
    const __nv_bfloat16* __restrict__ Ahi, const __nv_bfloat16* __restrict__ Alo, int lda,
    const __nv_bfloat16* __restrict__ Bhi, const __nv_bfloat16* __restrict__ Blo, int ldb,
    float* __restrict__ Cf, __nv_bfloat16* __restrict__ Chi, __nv_bfloat16* __restrict__ Clo,
    int ldc, int K, int qcols)
{
    extern __shared__ char smem[];
    uint32_t su = smem_u32(smem);
    constexpr uint32_t PLA = 64 * PAD * 2;
    constexpr uint32_t PLB = 128 * PAD * 2;
    constexpr uint32_t STG = 2 * PLA + 2 * PLB;

    int m0 = blockIdx.y * 64, n0 = blockIdx.x * 128;
    int tid = threadIdx.x, wid = tid >> 5, lid = tid & 31;
    int wm = (wid & 1) * 32, wn = (wid >> 1) * 32;
    int g = lid >> 2, t2 = (lid & 3) * 2, rsel = lid & 7, mat = lid >> 3;

    uint32_t a_off[2], b2_off[2];
#pragma unroll
    for (int mf = 0; mf < 2; mf++)
        a_off[mf] = (uint32_t)(((wm + mf * 16 + (mat & 1) * 8 + rsel) * PAD + (mat >> 1) * 8) * 2);
#pragma unroll
    for (int p = 0; p < 2; p++)
        b2_off[p] = (uint32_t)(((wn + p * 16 + (mat >> 1) * 8 + rsel) * PAD + (mat & 1) * 8) * 2);

    auto issue = [&](int kc, int st) {
        uint32_t base = su + st * STG;
        int k0 = kc * 64;
#pragma unroll
        for (int i = 0; i < 2; i++) {
            int idx = tid + i * 256;
            int row = idx >> 3, ch = idx & 7;
            uint32_t d = base + (uint32_t)((row * PAD + ch * 8) * 2);
            cp16(d,       Ahi + (size_t)(m0 + row) * lda + k0 + ch * 8);
            cp16(d + PLA, Alo + (size_t)(m0 + row) * lda + k0 + ch * 8);
        }
#pragma unroll
        for (int i = 0; i < 4; i++) {
            int idx = tid + i * 256;
            int row = idx >> 3, ch = idx & 7;
            uint32_t d = base + 2 * PLA + (uint32_t)((row * PAD + ch * 8) * 2);
            cp16(d,       Bhi + (size_t)(n0 + row) * ldb + k0 + ch * 8);
            cp16(d + PLB, Blo + (size_t)(n0 + row) * ldb + k0 + ch * 8);
        }
        CP_COMMIT();
    };

    float acc[2][4][4];
#pragma unroll
    for (int mf = 0; mf < 2; mf++)
#pragma unroll
        for (int nf = 0; nf < 4; nf++)
#pragma unroll
            for (int j = 0; j < 4; j++) acc[mf][nf][j] = 0.0f;

    int NKC = K / 64;
    issue(0, 0);
    for (int kc = 0; kc < NKC; kc++) {
        int st = kc & 1;
        if (kc + 1 < NKC) { issue(kc + 1, st ^ 1); CP_WAIT(1); }
        else              { CP_WAIT(0); }
        __syncthreads();
        uint32_t ah = su + st * STG, al = ah + PLA;
        uint32_t bh = su + st * STG + 2 * PLA, bl = bh + PLB;
#pragma unroll
        for (int ks = 0; ks < 4; ks++) {
            uint32_t kb = (uint32_t)(ks * 32);
            uint32_t fh[2][4], fl[2][4];
            ldsm_x4(fh[0], ah + a_off[0] + kb);
            ldsm_x4(fh[1], ah + a_off[1] + kb);
            ldsm_x4(fl[0], al + a_off[0] + kb);
            ldsm_x4(fl[1], al + a_off[1] + kb);
#pragma unroll
            for (int p = 0; p < 2; p++) {
                uint32_t bb[4], cc[4];
                ldsm_x4(bb, bh + b2_off[p] + kb);
                mma16816(acc[0][2 * p],     fh[0], bb[0], bb[1]);
                mma16816(acc[1][2 * p],     fh[1], bb[0], bb[1]);
                mma16816(acc[0][2 * p + 1], fh[0], bb[2], bb[3]);
                mma16816(acc[1][2 * p + 1], fh[1], bb[2], bb[3]);
                mma16816(acc[0][2 * p],     fl[0], bb[0], bb[1]);
                mma16816(acc[1][2 * p],     fl[1], bb[0], bb[1]);
                mma16816(acc[0][2 * p + 1], fl[0], bb[2], bb[3]);
                mma16816(acc[1][2 * p + 1], fl[1], bb[2], bb[3]);
                ldsm_x4(cc, bl + b2_off[p] + kb);
                mma16816(acc[0][2 * p],     fh[0], cc[0], cc[1]);
                mma16816(acc[1][2 * p],     fh[1], cc[0], cc[1]);
                mma16816(acc[0][2 * p + 1], fh[0], cc[2], cc[3]);
                mma16816(acc[1][2 * p + 1], fh[1], cc[2], cc[3]);
            }
        }
        __syncthreads();
    }

    // epilogue
#pragma unroll
    for (int mf = 0; mf < 2; mf++) {
        int r0 = m0 + wm + mf * 16 + g;
#pragma unroll
        for (int nf = 0; nf < 4; nf++) {
            int col = n0 + wn + nf * 8 + t2;
            float sc = 1.0f;
            if (SPLIT_OUT && col < qcols) sc = QSCALE;
            float v0 = acc[mf][nf][0] * sc, v1 = acc[mf][nf][1] * sc;
            float v2 = acc[mf][nf][2] * sc, v3 = acc[mf][nf][3] * sc;
            if (SPLIT_OUT) {
                uint32_t h0 = pkf(v0, v1);
                uint32_t l0 = pkf(v0 - bf_lo_as_f(h0), v1 - bf_hi_as_f(h0));
                *(uint32_t*)(Chi + (size_t)r0 * ldc + col) = h0;
                *(uint32_t*)(Clo + (size_t)r0 * ldc + col) = l0;
                uint32_t h1 = pkf(v2, v3);
                uint32_t l1 = pkf(v2 - bf_lo_as_f(h1), v3 - bf_hi_as_f(h1));
                *(uint32_t*)(Chi + (size_t)(r0 + 8) * ldc + col) = h1;
                *(uint32_t*)(Clo + (size_t)(r0 + 8) * ldc + col) = l1;
            } else {
                *(float2*)(Cf + (size_t)r0 * ldc + col) = make_float2(v0, v1);
                *(float2*)(Cf + (size_t)(r0 + 8) * ldc + col) = make_float2(v2, v3);
            }
        }
    }
}

// ---------------- fused attention (split K/V prefetch bursts) ----------------
__global__ void __launch_bounds__(256) flash_attn()
{
    extern __shared__ char smem[];
    __shared__ float ssum;
    uint32_t su = smem_u32(smem);
    constexpr uint32_t QLO   = 128 * PAD * 2;
    constexpr uint32_t KBASE = 2 * 128 * PAD * 2;
    constexpr uint32_t KSTG  = 2 * 128 * PAD * 2;
    constexpr uint32_t VBASE = KBASE + 2 * KSTG;
    constexpr uint32_t VPL   = 64 * PADV * 2;
    constexpr uint32_t VSTG  = 2 * VPL;
    constexpr int NSPLIT_T = (TLEN / 128) / 2;   // 16 key tiles per split

    int h = blockIdx.y;
    int m0 = blockIdx.x * 128;
    int z = blockIdx.z;
    int tbase = z * NSPLIT_T;
    float* Oglob = z ? g_attn2 : g_attn;
    int tid = threadIdx.x, wid = tid >> 5, lid = tid & 31;
    int wm = (wid & 3) * 32, wn = (wid >> 2) * 64;
    int g = lid >> 2, t2 = (lid & 3) * 2, rsel = lid & 7, mat = lid >> 3;

    // load Q tile planes (pre-scaled by 0.125*log2e)
#pragma unroll
    for (int i = 0; i < 4; i++) {
        int idx = tid + i * 256;
        int row = idx >> 3, ch = idx & 7;
        size_t src = (size_t)(m0 + row) * QKV_N + h * HD + ch * 8;
        uint32_t d = (uint32_t)((row * PAD + ch * 8) * 2);
        *(uint4*)(smem + d)       = *(const uint4*)(g_qkv_hi + src);
        *(uint4*)(smem + QLO + d) = *(const uint4*)(g_qkv_lo + src);
    }
    if (tid == 0) ssum = 0.0f;

    uint32_t a_off[2], b2_off[4], v2_off[4];
#pragma unroll
    for (int mf = 0; mf < 2; mf++)
        a_off[mf] = (uint32_t)(((wm + mf * 16 + (mat & 1) * 8 + rsel) * PAD + (mat >> 1) * 8) * 2);
#pragma unroll
    for (int p = 0; p < 4; p++) {
        b2_off[p] = (uint32_t)(((wn + p * 16 + (mat >> 1) * 8 + rsel) * PAD + (mat & 1) * 8) * 2);
        v2_off[p] = (uint32_t)(((p * 16 + (mat >> 1) * 8 + rsel) * PADV + wn + (mat & 1) * 8) * 2);
    }

    auto issueK = [&](int t, int st) {
        int s0 = t * 128;
        uint32_t kb = su + KBASE + st * KSTG;
#pragma unroll
        for (int i = 0; i < 4; i++) {
            int idx = tid + i * 256;
            int row = idx >> 3, ch = idx & 7;
            size_t src = (size_t)(s0 + row) * QKV_N + DIM + h * HD + ch * 8;
            uint32_t d = kb + (uint32_t)((row * PAD + ch * 8) * 2);
            cp16(d,                 g_qkv_hi + src);
            cp16(d + 128 * PAD * 2, g_qkv_lo + src);
        }
    };
    auto issueV = [&](int t, int st) {
        int s0 = t * 128;
        uint32_t vb = su + VBASE + st * VSTG;
#pragma unroll
        for (int i = 0; i < 4; i++) {
            int idx = tid + i * 256;
            int dd = idx >> 4, ch = idx & 15;
            size_t src = ((size_t)h * HD + dd) * TLEN + s0 + ch * 8;
            uint32_t d = vb + (uint32_t)((dd * PADV + ch * 8) * 2);
            cp16(d,       g_vt_hi + src);
            cp16(d + VPL, g_vt_lo + src);
        }
    };

    issueK(tbase, 0);
    issueV(tbase, 0);
    CP_COMMIT();
    __syncthreads();

    // hoist Q-hi fragments (invariant over key tiles)
    uint32_t Qh[4][2][4];
#pragma unroll
    for (int ks = 0; ks < 4; ks++)
#pragma unroll
        for (int mf = 0; mf < 2; mf++)
            ldsm_x4(Qh[ks][mf], su + a_off[mf] + ks * 32);

    float O[2][8][4];
#pragma unroll
    for (int mf = 0; mf < 2; mf++)
#pragma unroll
        for (int nf = 0; nf < 8; nf++)
#pragma unroll
            for (int j = 0; j < 4; j++) O[mf][nf][j] = 0.0f;
    float sE[4] = {0.0f, 0.0f, 0.0f, 0.0f};

    for (int tt = 0; tt < NSPLIT_T; tt++) {
        int st = tt & 1;
        if (tt + 1 < NSPLIT_T) { issueK(tbase + tt + 1, st ^ 1); CP_COMMIT(); CP_WAIT(1); }
        else                   { CP_WAIT(0); }
        __syncthreads();

        uint32_t ql = su + QLO;
        uint32_t kh = su + KBASE + st * KSTG, kl = kh + 128 * PAD * 2;
        uint32_t vh = su + VBASE + st * VSTG, vl = vh + VPL;

        // ---- S = Q @ K^T (3-pass; Q-lo loaded once per ks) ----
        float E[2][8][4];
#pragma unroll
        for (int mf = 0; mf < 2; mf++)
#pragma unroll
            for (int nf = 0; nf < 8; nf++)
#pragma unroll
                for (int j = 0; j < 4; j++) E[mf][nf][j] = 0.0f;
#pragma unroll
        for (int ks = 0; ks < 4; ks++) {
            uint32_t kb = (uint32_t)(ks * 32);
            uint32_t fl[2][4];
            ldsm_x4(fl[0], ql + a_off[0] + kb);
            ldsm_x4(fl[1], ql + a_off[1] + kb);
#pragma unroll
            for (int p = 0; p < 4; p += 2) {
                uint32_t bb0[4], bb1[4], cc0[4], cc1[4];
                ldsm_x4(bb0, kh + b2_off[p] + kb);
                ldsm_x4(bb1, kh + b2_off[p + 1] + kb);
                ldsm_x4(cc0, kl + b2_off[p] + kb);
                ldsm_x4(cc1, kl + b2_off[p + 1] + kb);
                // pass 1: Qhi * Khi
                mma16816(E[0][2 * p],     Qh[ks][0], bb0[0], bb0[1]);
                mma16816(E[1][2 * p],     Qh[ks][1], bb0[0], bb0[1]);
                mma16816(E[0][2 * p + 1], Qh[ks][0], bb0[2], bb0[3]);
                mma16816(E[1][2 * p + 1], Qh[ks][1], bb0[2], bb0[3]);
                mma16816(E[0][2 * p + 2], Qh[ks][0], bb1[0], bb1[1]);
                mma16816(E[1][2 * p + 2], Qh[ks][1], bb1[0], bb1[1]);
                mma16816(E[0][2 * p + 3], Qh[ks][0], bb1[2], bb1[3]);
                mma16816(E[1][2 * p + 3], Qh[ks][1], bb1[2], bb1[3]);
                // pass 2: Qhi * Klo
                mma16816(E[0][2 * p],     Qh[ks][0], cc0[0], cc0[1]);
                mma16816(E[1][2 * p],     Qh[ks][1], cc0[0], cc0[1]);
                mma16816(E[0][2 * p + 1], Qh[ks][0], cc0[2], cc0[3]);
                mma16816(E[1][2 * p + 1], Qh[ks][1], cc0[2], cc0[3]);
                mma16816(E[0][2 * p + 2], Qh[ks][0], cc1[0], cc1[1]);
                mma16816(E[1][2 * p + 2], Qh[ks][1], cc1[0], cc1[1]);
                mma16816(E[0][2 * p + 3], Qh[ks][0], cc1[2], cc1[3]);
                mma16816(E[1][2 * p + 3], Qh[ks][1], cc1[2], cc1[3]);
                // pass 3: Qlo * Khi
                mma16816(E[0][2 * p],     fl[0], bb0[0], bb0[1]);
                mma16816(E[1][2 * p],     fl[1], bb0[0], bb0[1]);
                mma16816(E[0][2 * p + 1], fl[0], bb0[2], bb0[3]);
                mma16816(E[1][2 * p + 1], fl[1], bb0[2], bb0[3]);
                mma16816(E[0][2 * p + 2], fl[0], bb1[0], bb1[1]);
                mma16816(E[1][2 * p + 2], fl[1], bb1[0], bb1[1]);
                mma16816(E[0][2 * p + 3], fl[0], bb1[2], bb1[3]);
                mma16816(E[1][2 * p + 3], fl[1], bb1[2], bb1[3]);
            }
        }
        // prefetch next tile's V now (lands during exp/PV; own commit group)
        if (tt + 1 < NSPLIT_T) { issueV(tbase + tt + 1, st ^ 1); CP_COMMIT(); }

        // ---- PV with per-j exp2 + partial sums ----
#pragma unroll
        for (int j = 0; j < 4; j++) {
            float s = 0.0f;
#pragma unroll
            for (int mf = 0; mf < 2; mf++)
#pragma unroll
                for (int q = 0; q < 2; q++)
#pragma unroll
                    for (int jj = 0; jj < 4; jj++) {
                        float e = ex2f(E[mf][2 * j + q][jj]);
                        E[mf][2 * j + q][jj] = e;
                        s += e;
                    }
            sE[j] += s;

            uint32_t Ph[2][4], vv[4][4], ww[4][4];
#pragma unroll
            for (int mf = 0; mf < 2; mf++) {
                float* e0 = E[mf][2 * j];
                float* e1 = E[mf][2 * j + 1];
                Ph[mf][0] = pkf(e0[0], e0[1]);
                Ph[mf][1] = pkf(e0[2], e0[3]);
                Ph[mf][2] = pkf(e1[0], e1[1]);
                Ph[mf][3] = pkf(e1[2], e1[3]);
            }
#pragma unroll
            for (int p = 0; p < 4; p++) ldsm_x4(vv[p], vh + v2_off[p] + j * 32);
#pragma unroll
            for (int p = 0; p < 4; p++) ldsm_x4(ww[p], vl + v2_off[p] + j * 32);
            // pass 1: Phi * Vhi
#pragma unroll
            for (int p = 0; p < 4; p++) {
                mma16816(O[0][2 * p],     Ph[0], vv[p][0], vv[p][1]);
                mma16816(O[1][2 * p],     Ph[1], vv[p][0], vv[p][1]);
                mma16816(O[0][2 * p + 1], Ph[0], vv[p][2], vv[p][3]);
                mma16816(O[1][2 * p + 1], Ph[1], vv[p][2], vv[p][3]);
            }
            // pass 2: Phi * Vlo (Pl pack overlaps)
#pragma unroll
            for (int p = 0; p < 4; p++) {
                mma16816(O[0][2 * p],     Ph[0], ww[p][0], ww[p][1]);
                mma16816(O[1][2 * p],     Ph[1], ww[p][0], ww[p][1]);
                mma16816(O[0][2 * p + 1], Ph[0], ww[p][2], ww[p][3]);
                mma16816(O[1][2 * p + 1], Ph[1], ww[p][2], ww[p][3]);
            }
            // Pl residual pack
            uint32_t Pl[2][4];
#pragma unroll
            for (int mf = 0; mf < 2; mf++) {
                float* e0 = E[mf][2 * j];
                float* e1 = E[mf][2 * j + 1];
                Pl[mf][0] = pkf(e0[0] - bf_lo_as_f(Ph[mf][0]), e0[1] - bf_hi_as_f(Ph[mf][0]));
                Pl[mf][1] = pkf(e0[2] - bf_lo_as_f(Ph[mf][1]), e0[3] - bf_hi_as_f(Ph[mf][1]));
                Pl[mf][2] = pkf(e1[0] - bf_lo_as_f(Ph[mf][2]), e1[1] - bf_hi_as_f(Ph[mf][2]));
                Pl[mf][3] = pkf(e1[2] - bf_lo_as_f(Ph[mf][3]), e1[3] - bf_hi_as_f(Ph[mf][3]));
            }
            // pass 3: Plo * Vhi
#pragma unroll
            for (int p = 0; p < 4; p++) {
                mma16816(O[0][2 * p],     Pl[0], vv[p][0], vv[p][1]);
                mma16816(O[1][2 * p],     Pl[1], vv[p][0], vv[p][1]);
                mma16816(O[0][2 * p + 1], Pl[0], vv[p][2], vv[p][3]);
                mma16816(O[1][2 * p + 1], Pl[1], vv[p][2], vv[p][3]);
            }
        }
        __syncthreads();
    }

    // ---- exp-sum reduction ----
    float sumE = (sE[0] + sE[1]) + (sE[2] + sE[3]);
#pragma unroll
    for (int off = 16; off > 0; off >>= 1)
        sumE += __shfl_xor_sync(0xffffffffu, sumE, off);
    if (lid == 0) atomicAdd(&ssum, sumE);

    // ---- O reduction across the two n-warp halves + fp32 store ----
    float* Obuf = (float*)(smem + KBASE);
    if (wid >= 4) {
#pragma unroll
        for (int mf = 0; mf < 2; mf++) {
            int r = wm + mf * 16 + g;
#pragma unroll
            for (int nf = 0; nf < 8; nf++) {
                int c = nf * 8 + t2;
                *(float2*)(Obuf + r * HD + c) = make_float2(O[mf][nf][0], O[mf][nf][1]);
                *(float2*)(Obuf + (r + 8) * HD + c) = make_float2(O[mf][nf][2], O[mf][nf][3]);
            }
        }
    }
    __syncthreads();
    if (tid == 0) atomicAdd(&g_sum[h], ssum);
    if (wid < 4) {
#pragma unroll
        for (int mf = 0; mf < 2; mf++) {
            int r = wm + mf * 16 + g;
#pragma unroll
            for (int nf = 0; nf < 8; nf++) {
                int c = nf * 8 + t2;
                float2 p0 = *(float2*)(Obuf + r * HD + c);
                float2 p1 = *(float2*)(Obuf + (r + 8) * HD + c);
                *(float2*)(Oglob + (size_t)(m0 + r) * DIM + h * HD + c) =
                    make_float2(O[mf][nf][0] + p0.x, O[mf][nf][1] + p0.y);
                *(float2*)(Oglob + (size_t)(m0 + r + 8) * DIM + h * HD + c) =
                    make_float2(O[mf][nf][2] + p1.x, O[mf][nf][3] + p1.y);
            }
        }
    }
}

// combine the two KV splits, normalize by per-head exp-sum, split to bf16 planes
__global__ void __launch_bounds__(256) scale_split() {
    __shared__ float inv[NH];
    if (threadIdx.x < NH) inv[threadIdx.x] = 1.0f / g_sum[threadIdx.x];
    __syncthreads();
    size_t i = (size_t)blockIdx.x * 256 + threadIdx.x;
    float4 v = ((const float4*)g_attn)[i];
    float4 w = ((const float4*)g_attn2)[i];
    int col = (int)((i * 4) & (DIM - 1));
    float s = inv[col >> 6];
    v.x = (v.x + w.x) * s; v.y = (v.y + w.y) * s;
    v.z = (v.z + w.z) * s; v.w = (v.w + w.w) * s;
    uint32_t h0 = pkf(v.x, v.y), h1 = pkf(v.z, v.w);
    uint32_t l0 = pkf(v.x - bf_lo_as_f(h0), v.y - bf_hi_as_f(h0));
    uint32_t l1 = pkf(v.z - bf_lo_as_f(h1), v.w - bf_hi_as_f(h1));
    ((uint2*)g_at_hi)[i] = make_uint2(h0, h1);
    ((uint2*)g_at_lo)[i] = make_uint2(l0, l1);
}

// ---------------- launch ----------------
extern "C" void kernel_launch(void* const* d_in, const int* in_sizes, int n_in,
                              void* d_out, int out_size)
{
    const float* x = (const float*)d_in[0];
    const float* W_in = (const float*)d_in[1];
    const float* W_out = (const float*)d_in[2];
    float* out = (float*)d_out;

    __nv_bfloat16 *xs_hi, *xs_lo, *wi_hi, *wi_lo, *wo_hi, *wo_lo;
    __nv_bfloat16 *qkv_hi, *qkv_lo, *at_hi, *at_lo;
    cudaGetSymbolAddress((void**)&xs_hi, g_xs_hi);
    cudaGetSymbolAddress((void**)&xs_lo, g_xs_lo);
    cudaGetSymbolAddress((void**)&wi_hi, g_wi_hi);
    cudaGetSymbolAddress((void**)&wi_lo, g_wi_lo);
    cudaGetSymbolAddress((void**)&wo_hi, g_wo_hi);
    cudaGetSymbolAddress((void**)&wo_lo, g_wo_lo);
    cudaGetSymbolAddress((void**)&qkv_hi, g_qkv_hi);
    cudaGetSymbolAddress((void**)&qkv_lo, g_qkv_lo);
    cudaGetSymbolAddress((void**)&at_hi, g_at_hi);
    cudaGetSymbolAddress((void**)&at_lo, g_at_lo);

    const int SMEMG = 2 * (2 * 64 * PAD * 2 + 2 * 128 * PAD * 2);  // 110592
    const int SMEMF = 2 * 128 * PAD * 2 + 2 * (2 * 128 * PAD * 2)
                    + 2 * (2 * 64 * PADV * 2);                     // 180224
    cudaFuncSetAttribute(gemm_bf16<true>,
                         cudaFuncAttributeMaxDynamicSharedMemorySize, SMEMG);
    cudaFuncSetAttribute(gemm_bf16<false>,
                         cudaFuncAttributeMaxDynamicSharedMemorySize, SMEMG);
    cudaFuncSetAttribute(flash_attn,
                         cudaFuncAttributeMaxDynamicSharedMemorySize, SMEMF);

    init_kernel<<<1, 32>>>();

    // split all inputs into bf16 hi/lo planes (single launch)
    const int N4ALL = N4_X + N4_WI + N4_WO;
    split_all<<<(N4ALL + 255) / 256, 256>>>(x, W_in, W_out);

    // qkv = x @ W_in^T ; q pre-scaled by 0.125*log2e; split planes out
    gemm_bf16<true><<<dim3(QKV_N / 128, TLEN / 64), 256, SMEMG>>>(
        xs_hi, xs_lo, DIM, wi_hi, wi_lo, DIM,
        nullptr, qkv_hi, qkv_lo, QKV_N, DIM, DIM);

    // V^T per head (both planes)
    transpose_v<<<dim3(TLEN / 64, NH), 256>>>();

    // fused attention, KV split x2 -> two unnormalized fp32 partials + exp-sums
    flash_attn<<<dim3(TLEN / 128, NH, 2), 256, SMEMF>>>();

    // combine splits, normalize, split to bf16 planes
    scale_split<<<TLEN * DIM / 4 / 256, 256>>>();

    // out = attn @ W_out^T
    gemm_bf16<false><<<dim3(DIM / 128, TLEN / 64), 256, SMEMG>>>(
        at_hi, at_lo, DIM, wo_hi, wo_lo, DIM,
        out, nullptr, nullptr, DIM, DIM, 0);
}

// round 17
// speedup vs baseline: 1.0428x; 1.0135x over previous
#include <cuda_runtime.h>
#include <cuda_bf16.h>
#include <cstdint>

#define TLEN 4096
#define DIM 1024
#define NH 16
#define HD 64
#define QKV_N 3072
#define PAD 72      // bf16 elems per smem row (144 B)
#define QSCALE 0.18033688011112042f   // 0.125 * log2(e)

// ---------------- scratch (allocation-free) ----------------
__device__ __nv_bfloat16 g_xs_hi[(size_t)TLEN * DIM],  g_xs_lo[(size_t)TLEN * DIM];
__device__ __nv_bfloat16 g_wi_hi[(size_t)QKV_N * DIM], g_wi_lo[(size_t)QKV_N * DIM];
__device__ __nv_bfloat16 g_wo_hi[(size_t)DIM * DIM],   g_wo_lo[(size_t)DIM * DIM];
__device__ __nv_bfloat16 g_qkv_hi[(size_t)TLEN * QKV_N], g_qkv_lo[(size_t)TLEN * QKV_N];
__device__ __nv_bfloat16 g_at_hi[(size_t)TLEN * DIM],  g_at_lo[(size_t)TLEN * DIM];
__device__ float g_attn[(size_t)TLEN * DIM];
__device__ float g_attn2[(size_t)TLEN * DIM];
__device__ float g_sum[NH];

// ---------------- helpers ----------------
__device__ __forceinline__ uint32_t smem_u32(const void* p) {
    uint32_t a;
    asm("{ .reg .u64 t; cvta.to.shared.u64 t, %1; cvt.u32.u64 %0, t; }" : "=r"(a) : "l"(p));
    return a;
}
__device__ __forceinline__ uint32_t pkf(float a, float b) {
    uint32_t r;
    asm("cvt.rn.bf16x2.f32 %0, %1, %2;" : "=r"(r) : "f"(b), "f"(a));
    return r;
}
__device__ __forceinline__ float bf_lo_as_f(uint32_t u) { return __uint_as_float(u << 16); }
__device__ __forceinline__ float bf_hi_as_f(uint32_t u) { return __uint_as_float(u & 0xffff0000u); }
__device__ __forceinline__ float ex2f(float x) {
    float y;
    asm("ex2.approx.f32 %0, %1;" : "=f"(y) : "f"(x));
    return y;
}

__device__ __forceinline__ void ldsm_x4(uint32_t* r, uint32_t addr) {
    asm volatile("ldmatrix.sync.aligned.m8n8.x4.shared.b16 {%0,%1,%2,%3}, [%4];"
                 : "=r"(r[0]), "=r"(r[1]), "=r"(r[2]), "=r"(r[3]) : "r"(addr));
}
__device__ __forceinline__ void ldsm_x4t(uint32_t* r, uint32_t addr) {
    asm volatile("ldmatrix.sync.aligned.m8n8.x4.trans.shared.b16 {%0,%1,%2,%3}, [%4];"
                 : "=r"(r[0]), "=r"(r[1]), "=r"(r[2]), "=r"(r[3]) : "r"(addr));
}
__device__ __forceinline__ void mma16816(float* c, const uint32_t* a, uint32_t b0, uint32_t b1) {
    asm volatile(
        "mma.sync.aligned.m16n8k16.row.col.f32.bf16.bf16.f32 "
        "{%0,%1,%2,%3}, {%4,%5,%6,%7}, {%8,%9}, {%0,%1,%2,%3};"
        : "+f"(c[0]), "+f"(c[1]), "+f"(c[2]), "+f"(c[3])
        : "r"(a[0]), "r"(a[1]), "r"(a[2]), "r"(a[3]), "r"(b0), "r"(b1));
}
__device__ __forceinline__ void cp16(uint32_t dst, const void* src) {
    asm volatile("cp.async.cg.shared.global [%0], [%1], 16;" :: "r"(dst), "l"(src));
}
#define CP_COMMIT() asm volatile("cp.async.commit_group;" ::: "memory")
#define CP_WAIT(N)  asm volatile("cp.async.wait_group %0;" :: "n"(N) : "memory")

__global__ void init_kernel() {
    if (threadIdx.x < NH) g_sum[threadIdx.x] = 0.0f;
}

// merged fp32 -> split bf16 hi/lo planes for x, W_in, W_out (one launch)
#define N4_X  (TLEN * DIM / 4)
#define N4_WI (QKV_N * DIM / 4)
#define N4_WO (DIM * DIM / 4)
__global__ void __launch_bounds__(256) split_all(const float* __restrict__ x,
                                                 const float* __restrict__ wi,
                                                 const float* __restrict__ wo) {
    int i = blockIdx.x * 256 + threadIdx.x;
    const float* src;
    __nv_bfloat16 *hi, *lo;
    int idx;
    if (i < N4_X) {
        src = x; hi = g_xs_hi; lo = g_xs_lo; idx = i;
    } else if (i < N4_X + N4_WI) {
        src = wi; hi = g_wi_hi; lo = g_wi_lo; idx = i - N4_X;
    } else if (i < N4_X + N4_WI + N4_WO) {
        src = wo; hi = g_wo_hi; lo = g_wo_lo; idx = i - N4_X - N4_WI;
    } else {
        return;
    }
    float4 v = ((const float4*)src)[idx];
    uint32_t h0 = pkf(v.x, v.y), h1 = pkf(v.z, v.w);
    uint32_t l0 = pkf(v.x - bf_lo_as_f(h0), v.y - bf_hi_as_f(h0));
    uint32_t l1 = pkf(v.z - bf_lo_as_f(h1), v.w - bf_hi_as_f(h1));
    ((uint2*)hi)[idx] = make_uint2(h0, h1);
    ((uint2*)lo)[idx] = make_uint2(l0, l1);
}

// ---------------- split-bf16 3-pass GEMM: 64x128 tile, 2 CTAs/SM (untouched) ----------------
template <bool SPLIT_OUT>
__global__ void __launch_bounds__(256, 2) gemm_bf16(
    const __nv_bfloat16* __restrict__ Ahi, const __nv_bfloat16* __restrict__ Alo, int lda,
    const __nv_bfloat16* __restrict__ Bhi, const __nv_bfloat16* __restrict__ Blo, int ldb,
    float* __restrict__ Cf, __nv_bfloat16* __restrict__ Chi, __nv_bfloat16* __restrict__ Clo,
    int ldc, int K, int qcols)
{
    extern __shared__ char smem[];
    uint32_t su = smem_u32(smem);
    constexpr uint32_t PLA = 64 * PAD * 2;
    constexpr uint32_t PLB = 128 * PAD * 2;
    constexpr uint32_t STG = 2 * PLA + 2 * PLB;

    int m0 = blockIdx.y * 64, n0 = blockIdx.x * 128;
    int tid = threadIdx.x, wid = tid >> 5, lid = tid & 31;
    int wm = (wid & 1) * 32, wn = (wid >> 1) * 32;
    int g = lid >> 2, t2 = (lid & 3) * 2, rsel = lid & 7, mat = lid >> 3;

    uint32_t a_off[2], b2_off[2];
#pragma unroll
    for (int mf = 0; mf < 2; mf++)
        a_off[mf] = (uint32_t)(((wm + mf * 16 + (mat & 1) * 8 + rsel) * PAD + (mat >> 1) * 8) * 2);
#pragma unroll
    for (int p = 0; p < 2; p++)
        b2_off[p] = (uint32_t)(((wn + p * 16 + (mat >> 1) * 8 + rsel) * PAD + (mat & 1) * 8) * 2);

    auto issue = [&](int kc, int st) {
        uint32_t base = su + st * STG;
        int k0 = kc * 64;
#pragma unroll
        for (int i = 0; i < 2; i++) {
            int idx = tid + i * 256;
            int row = idx >> 3, ch = idx & 7;
            uint32_t d = base + (uint32_t)((row * PAD + ch * 8) * 2);
            cp16(d,       Ahi + (size_t)(m0 + row) * lda + k0 + ch * 8);
            cp16(d + PLA, Alo + (size_t)(m0 + row) * lda + k0 + ch * 8);
        }
#pragma unroll
        for (int i = 0; i < 4; i++) {
            int idx = tid + i * 256;
            int row = idx >> 3, ch = idx & 7;
            uint32_t d = base + 2 * PLA + (uint32_t)((row * PAD + ch * 8) * 2);
            cp16(d,       Bhi + (size_t)(n0 + row) * ldb + k0 + ch * 8);
            cp16(d + PLB, Blo + (size_t)(n0 + row) * ldb + k0 + ch * 8);
        }
        CP_COMMIT();
    };

    float acc[2][4][4];
#pragma unroll
    for (int mf = 0; mf < 2; mf++)
#pragma unroll
        for (int nf = 0; nf < 4; nf++)
#pragma unroll
            for (int j = 0; j < 4; j++) acc[mf][nf][j] = 0.0f;

    int NKC = K / 64;
    issue(0, 0);
    for (int kc = 0; kc < NKC; kc++) {
        int st = kc & 1;
        if (kc + 1 < NKC) { issue(kc + 1, st ^ 1); CP_WAIT(1); }
        else              { CP_WAIT(0); }
        __syncthreads();
        uint32_t ah = su + st * STG, al = ah + PLA;
        uint32_t bh = su + st * STG + 2 * PLA, bl = bh + PLB;
#pragma unroll
        for (int ks = 0; ks < 4; ks++) {
            uint32_t kb = (uint32_t)(ks * 32);
            uint32_t fh[2][4], fl[2][4];
            ldsm_x4(fh[0], ah + a_off[0] + kb);
            ldsm_x4(fh[1], ah + a_off[1] + kb);
            ldsm_x4(fl[0], al + a_off[0] + kb);
            ldsm_x4(fl[1], al + a_off[1] + kb);
#pragma unroll
            for (int p = 0; p < 2; p++) {
                uint32_t bb[4], cc[4];
                ldsm_x4(bb, bh + b2_off[p] + kb);
                mma16816(acc[0][2 * p],     fh[0], bb[0], bb[1]);
                mma16816(acc[1][2 * p],     fh[1], bb[0], bb[1]);
                mma16816(acc[0][2 * p + 1], fh[0], bb[2], bb[3]);
                mma16816(acc[1][2 * p + 1], fh[1], bb[2], bb[3]);
                mma16816(acc[0][2 * p],     fl[0], bb[0], bb[1]);
                mma16816(acc[1][2 * p],     fl[1], bb[0], bb[1]);
                mma16816(acc[0][2 * p + 1], fl[0], bb[2], bb[3]);
                mma16816(acc[1][2 * p + 1], fl[1], bb[2], bb[3]);
                ldsm_x4(cc, bl + b2_off[p] + kb);
                mma16816(acc[0][2 * p],     fh[0], cc[0], cc[1]);
                mma16816(acc[1][2 * p],     fh[1], cc[0], cc[1]);
                mma16816(acc[0][2 * p + 1], fh[0], cc[2], cc[3]);
                mma16816(acc[1][2 * p + 1], fh[1], cc[2], cc[3]);
            }
        }
        __syncthreads();
    }

    // epilogue
#pragma unroll
    for (int mf = 0; mf < 2; mf++) {
        int r0 = m0 + wm + mf * 16 + g;
#pragma unroll
        for (int nf = 0; nf < 4; nf++) {
            int col = n0 + wn + nf * 8 + t2;
            float sc = 1.0f;
            if (SPLIT_OUT && col < qcols) sc = QSCALE;
            float v0 = acc[mf][nf][0] * sc, v1 = acc[mf][nf][1] * sc;
            float v2 = acc[mf][nf][2] * sc, v3 = acc[mf][nf][3] * sc;
            if (SPLIT_OUT) {
                uint32_t h0 = pkf(v0, v1);
                uint32_t l0 = pkf(v0 - bf_lo_as_f(h0), v1 - bf_hi_as_f(h0));
                *(uint32_t*)(Chi + (size_t)r0 * ldc + col) = h0;
                *(uint32_t*)(Clo + (size_t)r0 * ldc + col) = l0;
                uint32_t h1 = pkf(v2, v3);
                uint32_t l1 = pkf(v2 - bf_lo_as_f(h1), v3 - bf_hi_as_f(h1));
                *(uint32_t*)(Chi + (size_t)(r0 + 8) * ldc + col) = h1;
                *(uint32_t*)(Clo + (size_t)(r0 + 8) * ldc + col) = l1;
            } else {
                *(float2*)(Cf + (size_t)r0 * ldc + col) = make_float2(v0, v1);
                *(float2*)(Cf + (size_t)(r0 + 8) * ldc + col) = make_float2(v2, v3);
            }
        }
    }
}

// ---------------- fused attention (V via trans-ldmatrix, no transpose kernel) ----------------
__global__ void __launch_bounds__(256) flash_attn()
{
    extern __shared__ char smem[];
    __shared__ float ssum;
    uint32_t su = smem_u32(smem);
    constexpr uint32_t QLO   = 128 * PAD * 2;
    constexpr uint32_t KBASE = 2 * 128 * PAD * 2;
    constexpr uint32_t KSTG  = 2 * 128 * PAD * 2;   // hi+lo
    constexpr uint32_t VBASE = KBASE + 2 * KSTG;
    constexpr uint32_t VPL   = 128 * PAD * 2;       // V plane: 128 s-rows x 144B
    constexpr uint32_t VSTG  = 2 * VPL;
    constexpr int NSPLIT_T = (TLEN / 128) / 2;      // 16 key tiles per split

    int h = blockIdx.y;
    int m0 = blockIdx.x * 128;
    int z = blockIdx.z;
    int tbase = z * NSPLIT_T;
    float* Oglob = z ? g_attn2 : g_attn;
    int tid = threadIdx.x, wid = tid >> 5, lid = tid & 31;
    int wm = (wid & 3) * 32, wn = (wid >> 2) * 64;
    int g = lid >> 2, t2 = (lid & 3) * 2, rsel = lid & 7, mat = lid >> 3;

    // load Q tile planes (pre-scaled by 0.125*log2e)
#pragma unroll
    for (int i = 0; i < 4; i++) {
        int idx = tid + i * 256;
        int row = idx >> 3, ch = idx & 7;
        size_t src = (size_t)(m0 + row) * QKV_N + h * HD + ch * 8;
        uint32_t d = (uint32_t)((row * PAD + ch * 8) * 2);
        *(uint4*)(smem + d)       = *(const uint4*)(g_qkv_hi + src);
        *(uint4*)(smem + QLO + d) = *(const uint4*)(g_qkv_lo + src);
    }
    if (tid == 0) ssum = 0.0f;

    uint32_t a_off[2], b2_off[4], vt_off[4];
#pragma unroll
    for (int mf = 0; mf < 2; mf++)
        a_off[mf] = (uint32_t)(((wm + mf * 16 + (mat & 1) * 8 + rsel) * PAD + (mat >> 1) * 8) * 2);
#pragma unroll
    for (int p = 0; p < 4; p++)
        b2_off[p] = (uint32_t)(((wn + p * 16 + (mat >> 1) * 8 + rsel) * PAD + (mat & 1) * 8) * 2);
    // trans-ldmatrix V offsets: stored [s][d]; matrix mat: kh=mat&1 (s-half), nb=mat>>1 (d-half)
#pragma unroll
    for (int p = 0; p < 4; p++)
        vt_off[p] = (uint32_t)(((wn + (mat & 1) * 8 + rsel) * PAD + p * 16 + (mat >> 1) * 8) * 2);

    auto issueK = [&](int t, int st) {
        int s0 = t * 128;
        uint32_t kb = su + KBASE + st * KSTG;
#pragma unroll
        for (int i = 0; i < 4; i++) {
            int idx = tid + i * 256;
            int row = idx >> 3, ch = idx & 7;
            size_t src = (size_t)(s0 + row) * QKV_N + DIM + h * HD + ch * 8;
            uint32_t d = kb + (uint32_t)((row * PAD + ch * 8) * 2);
            cp16(d,                 g_qkv_hi + src);
            cp16(d + 128 * PAD * 2, g_qkv_lo + src);
        }
    };
    auto issueV = [&](int t, int st) {
        int s0 = t * 128;
        uint32_t vb = su + VBASE + st * VSTG;
#pragma unroll
        for (int i = 0; i < 4; i++) {
            int idx = tid + i * 256;
            int row = idx >> 3, ch = idx & 7;
            size_t src = (size_t)(s0 + row) * QKV_N + 2 * DIM + h * HD + ch * 8;
            uint32_t d = vb + (uint32_t)((row * PAD + ch * 8) * 2);
            cp16(d,       g_qkv_hi + src);
            cp16(d + VPL, g_qkv_lo + src);
        }
    };

    issueK(tbase, 0);
    issueV(tbase, 0);
    CP_COMMIT();
    __syncthreads();

    // hoist Q-hi fragments (invariant over key tiles)
    uint32_t Qh[4][2][4];
#pragma unroll
    for (int ks = 0; ks < 4; ks++)
#pragma unroll
        for (int mf = 0; mf < 2; mf++)
            ldsm_x4(Qh[ks][mf], su + a_off[mf] + ks * 32);

    float O[2][8][4];
#pragma unroll
    for (int mf = 0; mf < 2; mf++)
#pragma unroll
        for (int nf = 0; nf < 8; nf++)
#pragma unroll
            for (int j = 0; j < 4; j++) O[mf][nf][j] = 0.0f;
    float sE[4] = {0.0f, 0.0f, 0.0f, 0.0f};

    for (int tt = 0; tt < NSPLIT_T; tt++) {
        int st = tt & 1;
        if (tt + 1 < NSPLIT_T) { issueK(tbase + tt + 1, st ^ 1); CP_COMMIT(); CP_WAIT(1); }
        else                   { CP_WAIT(0); }
        __syncthreads();

        uint32_t ql = su + QLO;
        uint32_t kh = su + KBASE + st * KSTG, kl = kh + 128 * PAD * 2;
        uint32_t vh = su + VBASE + st * VSTG, vl = vh + VPL;

        // ---- S = Q @ K^T (3-pass; Q-lo loaded once per ks) ----
        float E[2][8][4];
#pragma unroll
        for (int mf = 0; mf < 2; mf++)
#pragma unroll
            for (int nf = 0; nf < 8; nf++)
#pragma unroll
                for (int j = 0; j < 4; j++) E[mf][nf][j] = 0.0f;
#pragma unroll
        for (int ks = 0; ks < 4; ks++) {
            uint32_t kb = (uint32_t)(ks * 32);
            uint32_t fl[2][4];
            ldsm_x4(fl[0], ql + a_off[0] + kb);
            ldsm_x4(fl[1], ql + a_off[1] + kb);
#pragma unroll
            for (int p = 0; p < 4; p += 2) {
                uint32_t bb0[4], bb1[4], cc0[4], cc1[4];
                ldsm_x4(bb0, kh + b2_off[p] + kb);
                ldsm_x4(bb1, kh + b2_off[p + 1] + kb);
                ldsm_x4(cc0, kl + b2_off[p] + kb);
                ldsm_x4(cc1, kl + b2_off[p + 1] + kb);
                // pass 1: Qhi * Khi
                mma16816(E[0][2 * p],     Qh[ks][0], bb0[0], bb0[1]);
                mma16816(E[1][2 * p],     Qh[ks][1], bb0[0], bb0[1]);
                mma16816(E[0][2 * p + 1], Qh[ks][0], bb0[2], bb0[3]);
                mma16816(E[1][2 * p + 1], Qh[ks][1], bb0[2], bb0[3]);
                mma16816(E[0][2 * p + 2], Qh[ks][0], bb1[0], bb1[1]);
                mma16816(E[1][2 * p + 2], Qh[ks][1], bb1[0], bb1[1]);
                mma16816(E[0][2 * p + 3], Qh[ks][0], bb1[2], bb1[3]);
                mma16816(E[1][2 * p + 3], Qh[ks][1], bb1[2], bb1[3]);
                // pass 2: Qhi * Klo
                mma16816(E[0][2 * p],     Qh[ks][0], cc0[0], cc0[1]);
                mma16816(E[1][2 * p],     Qh[ks][1], cc0[0], cc0[1]);
                mma16816(E[0][2 * p + 1], Qh[ks][0], cc0[2], cc0[3]);
                mma16816(E[1][2 * p + 1], Qh[ks][1], cc0[2], cc0[3]);
                mma16816(E[0][2 * p + 2], Qh[ks][0], cc1[0], cc1[1]);
                mma16816(E[1][2 * p + 2], Qh[ks][1], cc1[0], cc1[1]);
                mma16816(E[0][2 * p + 3], Qh[ks][0], cc1[2], cc1[3]);
                mma16816(E[1][2 * p + 3], Qh[ks][1], cc1[2], cc1[3]);
                // pass 3: Qlo * Khi
                mma16816(E[0][2 * p],     fl[0], bb0[0], bb0[1]);
                mma16816(E[1][2 * p],     fl[1], bb0[0], bb0[1]);
                mma16816(E[0][2 * p + 1], fl[0], bb0[2], bb0[3]);
                mma16816(E[1][2 * p + 1], fl[1], bb0[2], bb0[3]);
                mma16816(E[0][2 * p + 2], fl[0], bb1[0], bb1[1]);
                mma16816(E[1][2 * p + 2], fl[1], bb1[0], bb1[1]);
                mma16816(E[0][2 * p + 3], fl[0], bb1[2], bb1[3]);
                mma16816(E[1][2 * p + 3], fl[1], bb1[2], bb1[3]);
            }
        }
        // prefetch next tile's V now (lands during exp/PV; own commit group)
        if (tt + 1 < NSPLIT_T) { issueV(tbase + tt + 1, st ^ 1); CP_COMMIT(); }

        // ---- PV with per-j exp2 + partial sums; V via trans-ldmatrix ----
#pragma unroll
        for (int j = 0; j < 4; j++) {
            float s = 0.0f;
#pragma unroll
            for (int mf = 0; mf < 2; mf++)
#pragma unroll
                for (int q = 0; q < 2; q++)
#pragma unroll
                    for (int jj = 0; jj < 4; jj++) {
                        float e = ex2f(E[mf][2 * j + q][jj]);
                        E[mf][2 * j + q][jj] = e;
                        s += e;
                    }
            sE[j] += s;

            uint32_t Ph[2][4], vv[4][4], ww[4][4];
#pragma unroll
            for (int mf = 0; mf < 2; mf++) {
                float* e0 = E[mf][2 * j];
                float* e1 = E[mf][2 * j + 1];
                Ph[mf][0] = pkf(e0[0], e0[1]);
                Ph[mf][1] = pkf(e0[2], e0[3]);
                Ph[mf][2] = pkf(e1[0], e1[1]);
                Ph[mf][3] = pkf(e1[2], e1[3]);
            }
            uint32_t jrow = (uint32_t)(j * 16 * PAD * 2);
#pragma unroll
            for (int p = 0; p < 4; p++) ldsm_x4t(vv[p], vh + vt_off[p] + jrow);
#pragma unroll
            for (int p = 0; p < 4; p++) ldsm_x4t(ww[p], vl + vt_off[p] + jrow);
            // pass 1: Phi * Vhi
#pragma unroll
            for (int p = 0; p < 4; p++) {
                mma16816(O[0][2 * p],     Ph[0], vv[p][0], vv[p][1]);
                mma16816(O[1][2 * p],     Ph[1], vv[p][0], vv[p][1]);
                mma16816(O[0][2 * p + 1], Ph[0], vv[p][2], vv[p][3]);
                mma16816(O[1][2 * p + 1], Ph[1], vv[p][2], vv[p][3]);
            }
            // pass 2: Phi * Vlo (Pl pack overlaps)
#pragma unroll
            for (int p = 0; p < 4; p++) {
                mma16816(O[0][2 * p],     Ph[0], ww[p][0], ww[p][1]);
                mma16816(O[1][2 * p],     Ph[1], ww[p][0], ww[p][1]);
                mma16816(O[0][2 * p + 1], Ph[0], ww[p][2], ww[p][3]);
                mma16816(O[1][2 * p + 1], Ph[1], ww[p][2], ww[p][3]);
            }
            // Pl residual pack
            uint32_t Pl[2][4];
#pragma unroll
            for (int mf = 0; mf < 2; mf++) {
                float* e0 = E[mf][2 * j];
                float* e1 = E[mf][2 * j + 1];
                Pl[mf][0] = pkf(e0[0] - bf_lo_as_f(Ph[mf][0]), e0[1] - bf_hi_as_f(Ph[mf][0]));
                Pl[mf][1] = pkf(e0[2] - bf_lo_as_f(Ph[mf][1]), e0[3] - bf_hi_as_f(Ph[mf][1]));
                Pl[mf][2] = pkf(e1[0] - bf_lo_as_f(Ph[mf][2]), e1[1] - bf_hi_as_f(Ph[mf][2]));
                Pl[mf][3] = pkf(e1[2] - bf_lo_as_f(Ph[mf][3]), e1[3] - bf_hi_as_f(Ph[mf][3]));
            }
            // pass 3: Plo * Vhi
#pragma unroll
            for (int p = 0; p < 4; p++) {
                mma16816(O[0][2 * p],     Pl[0], vv[p][0], vv[p][1]);
                mma16816(O[1][2 * p],     Pl[1], vv[p][0], vv[p][1]);
                mma16816(O[0][2 * p + 1], Pl[0], vv[p][2], vv[p][3]);
                mma16816(O[1][2 * p + 1], Pl[1], vv[p][2], vv[p][3]);
            }
        }
        __syncthreads();
    }

    // ---- exp-sum reduction ----
    float sumE = (sE[0] + sE[1]) + (sE[2] + sE[3]);
#pragma unroll
    for (int off = 16; off > 0; off >>= 1)
        sumE += __shfl_xor_sync(0xffffffffu, sumE, off);
    if (lid == 0) atomicAdd(&ssum, sumE);

    // ---- O reduction across the two n-warp halves + fp32 store ----
    float* Obuf = (float*)(smem + KBASE);
    if (wid >= 4) {
#pragma unroll
        for (int mf = 0; mf < 2; mf++) {
            int r = wm + mf * 16 + g;
#pragma unroll
            for (int nf = 0; nf < 8; nf++) {
                int c = nf * 8 + t2;
                *(float2*)(Obuf + r * HD + c) = make_float2(O[mf][nf][0], O[mf][nf][1]);
                *(float2*)(Obuf + (r + 8) * HD + c) = make_float2(O[mf][nf][2], O[mf][nf][3]);
            }
        }
    }
    __syncthreads();
    if (tid == 0) atomicAdd(&g_sum[h], ssum);
    if (wid < 4) {
#pragma unroll
        for (int mf = 0; mf < 2; mf++) {
            int r = wm + mf * 16 + g;
#pragma unroll
            for (int nf = 0; nf < 8; nf++) {
                int c = nf * 8 + t2;
                float2 p0 = *(float2*)(Obuf + r * HD + c);
                float2 p1 = *(float2*)(Obuf + (r + 8) * HD + c);
                *(float2*)(Oglob + (size_t)(m0 + r) * DIM + h * HD + c) =
                    make_float2(O[mf][nf][0] + p0.x, O[mf][nf][1] + p0.y);
                *(float2*)(Oglob + (size_t)(m0 + r + 8) * DIM + h * HD + c) =
                    make_float2(O[mf][nf][2] + p1.x, O[mf][nf][3] + p1.y);
            }
        }
    }
}

// combine the two KV splits, normalize by per-head exp-sum, split to bf16 planes
__global__ void __launch_bounds__(256) scale_split() {
    __shared__ float inv[NH];
    if (threadIdx.x < NH) inv[threadIdx.x] = 1.0f / g_sum[threadIdx.x];
    __syncthreads();
    size_t i = (size_t)blockIdx.x * 256 + threadIdx.x;
    float4 v = ((const float4*)g_attn)[i];
    float4 w = ((const float4*)g_attn2)[i];
    int col = (int)((i * 4) & (DIM - 1));
    float s = inv[col >> 6];
    v.x = (v.x + w.x) * s; v.y = (v.y + w.y) * s;
    v.z = (v.z + w.z) * s; v.w = (v.w + w.w) * s;
    uint32_t h0 = pkf(v.x, v.y), h1 = pkf(v.z, v.w);
    uint32_t l0 = pkf(v.x - bf_lo_as_f(h0), v.y - bf_hi_as_f(h0));
    uint32_t l1 = pkf(v.z - bf_lo_as_f(h1), v.w - bf_hi_as_f(h1));
    ((uint2*)g_at_hi)[i] = make_uint2(h0, h1);
    ((uint2*)g_at_lo)[i] = make_uint2(l0, l1);
}

// ---------------- launch ----------------
extern "C" void kernel_launch(void* const* d_in, const int* in_sizes, int n_in,
                              void* d_out, int out_size)
{
    const float* x = (const float*)d_in[0];
    const float* W_in = (const float*)d_in[1];
    const float* W_out = (const float*)d_in[2];
    float* out = (float*)d_out;

    __nv_bfloat16 *xs_hi, *xs_lo, *wi_hi, *wi_lo, *wo_hi, *wo_lo;
    __nv_bfloat16 *qkv_hi, *qkv_lo, *at_hi, *at_lo;
    cudaGetSymbolAddress((void**)&xs_hi, g_xs_hi);
    cudaGetSymbolAddress((void**)&xs_lo, g_xs_lo);
    cudaGetSymbolAddress((void**)&wi_hi, g_wi_hi);
    cudaGetSymbolAddress((void**)&wi_lo, g_wi_lo);
    cudaGetSymbolAddress((void**)&wo_hi, g_wo_hi);
    cudaGetSymbolAddress((void**)&wo_lo, g_wo_lo);
    cudaGetSymbolAddress((void**)&qkv_hi, g_qkv_hi);
    cudaGetSymbolAddress((void**)&qkv_lo, g_qkv_lo);
    cudaGetSymbolAddress((void**)&at_hi, g_at_hi);
    cudaGetSymbolAddress((void**)&at_lo, g_at_lo);

    const int SMEMG = 2 * (2 * 64 * PAD * 2 + 2 * 128 * PAD * 2);  // 110592
    const int SMEMF = 2 * 128 * PAD * 2 + 2 * (2 * 128 * PAD * 2)
                    + 2 * (2 * 128 * PAD * 2);                     // 184320
    cudaFuncSetAttribute(gemm_bf16<true>,
                         cudaFuncAttributeMaxDynamicSharedMemorySize, SMEMG);
    cudaFuncSetAttribute(gemm_bf16<false>,
                         cudaFuncAttributeMaxDynamicSharedMemorySize, SMEMG);
    cudaFuncSetAttribute(flash_attn,
                         cudaFuncAttributeMaxDynamicSharedMemorySize, SMEMF);

    init_kernel<<<1, 32>>>();

    // split all inputs into bf16 hi/lo planes (single launch)
    const int N4ALL = N4_X + N4_WI + N4_WO;
    split_all<<<(N4ALL + 255) / 256, 256>>>(x, W_in, W_out);

    // qkv = x @ W_in^T ; q pre-scaled by 0.125*log2e; split planes out
    gemm_bf16<true><<<dim3(QKV_N / 128, TLEN / 64), 256, SMEMG>>>(
        xs_hi, xs_lo, DIM, wi_hi, wi_lo, DIM,
        nullptr, qkv_hi, qkv_lo, QKV_N, DIM, DIM);

    // fused attention, KV split x2 (V consumed via trans-ldmatrix from qkv planes)
    flash_attn<<<dim3(TLEN / 128, NH, 2), 256, SMEMF>>>();

    // combine splits, normalize, split to bf16 planes
    scale_split<<<TLEN * DIM / 4 / 256, 256>>>();

    // out = attn @ W_out^T
    gemm_bf16<false><<<dim3(DIM / 128, TLEN / 64), 256, SMEMG>>>(
        at_hi, at_lo, DIM, wo_hi, wo_lo, DIM,
        out, nullptr, nullptr, DIM, DIM, 0);
}